// round 13
// baseline (speedup 1.0000x reference)
#include <cuda_runtime.h>
#include <cuda_bf16.h>
#include <cuda_fp16.h>
#include <cstdint>

// ---------------- problem constants ----------------
#define N_NODES   50000
#define N_EDGES   800000
#define IN_CH     256
#define HEADS     8
#define OUT_CH    32
#define HC        256          // HEADS*OUT_CH
#define NEG_SLOPE 0.2f

#define SCAN_CHUNK  512
#define SCAN_BLOCKS ((N_NODES + SCAN_CHUNK - 1) / SCAN_CHUNK)   // 98

// ---------------- device scratch ----------------
__device__ __half2 g_Whh[(size_t)N_NODES * (HC / 2)];    // 25.6 MB fp16 Wh
__device__ ushort  g_w16[HC * IN_CH];                    // 128 KB fp16 W
__device__ float g_eL[N_NODES * HEADS];
__device__ float g_eR[N_NODES * HEADS];
__device__ int   g_deg[N_NODES];
__device__ int   g_ptr[N_NODES + 1];
__device__ int   g_cursor[N_NODES];
__device__ int   g_csr_src[N_EDGES];
__device__ int   g_blocksum[SCAN_BLOCKS];
__device__ int   g_is64;

#define W_CVT_THREADS (HC * IN_CH / 8)        // 8,192

__device__ __forceinline__ uint32_t f2h2(float x, float y) {
    __half2 h = __floats2half2_rn(x, y);
    return *reinterpret_cast<uint32_t*>(&h);
}

// ---------------- W fp16 conversion (tiny, stream 0) ----------------
__global__ void cvt_w_kernel(const float* __restrict__ W) {
    int i = blockIdx.x * blockDim.x + threadIdx.x;
    if (i < W_CVT_THREADS) {
        size_t off = (size_t)i * 8;
        float4 a = *(const float4*)(W + off);
        float4 b = *(const float4*)(W + off + 4);
        uint4 h;
        h.x = f2h2(a.x, a.y); h.y = f2h2(a.z, a.w);
        h.z = f2h2(b.x, b.y); h.w = f2h2(b.z, b.w);
        *(uint4*)(g_w16 + off) = h;
    }
}

// ---------------- edge-chain init: detect dtype + zero deg (stream 2) ----
__global__ void init_edge_kernel(const int* ei_words) {
    int i = blockIdx.x * blockDim.x + threadIdx.x;
    if (i == 0) {
        int all0 = 1;
        for (int k = 0; k < 64; k++) {
            if (ei_words[2 * k + 1] != 0) { all0 = 0; break; }
        }
        g_is64 = all0;
    }
    if (i < N_NODES) g_deg[i] = 0;
}

// ---------------- tensor-core primitives ----------------
__device__ __forceinline__ void mma_f16(float* c, const uint32_t* a, const uint32_t* b) {
    asm volatile(
        "mma.sync.aligned.m16n8k16.row.col.f32.f16.f16.f32 "
        "{%0,%1,%2,%3}, {%4,%5,%6,%7}, {%8,%9}, {%0,%1,%2,%3};\n"
        : "+f"(c[0]), "+f"(c[1]), "+f"(c[2]), "+f"(c[3])
        : "r"(a[0]), "r"(a[1]), "r"(a[2]), "r"(a[3]), "r"(b[0]), "r"(b[1]));
}

__device__ __forceinline__ void ldsm_x4(uint32_t* r, uint32_t addr) {
    asm volatile("ldmatrix.sync.aligned.m8n8.x4.shared.b16 {%0,%1,%2,%3}, [%4];"
        : "=r"(r[0]), "=r"(r[1]), "=r"(r[2]), "=r"(r[3]) : "r"(addr));
}

// ---------------- GEMM: Wh = x @ W^T  (fp16 MMA + ldmatrix, 2-stage) -----
// Tile: BM=128, BN=128, BK=32. 8 warps (2x4). Warp tile 64x32 = one head.
// A converted fp32->fp16 inline at load; B pre-converted (g_w16).
#define SA 20          // smem row stride in uint32 (40 fp16 = 80B, LDSM conflict-free)
#define BUFW (128 * SA)

__global__ __launch_bounds__(256, 2)
void gemm_kernel(const float* __restrict__ x,
                 const float* __restrict__ aL, const float* __restrict__ aR) {
    __shared__ uint32_t As[2 * BUFW];
    __shared__ uint32_t Bs[2 * BUFW];

    const int t    = threadIdx.x;
    const int m0   = blockIdx.x * 128;
    const int n0   = blockIdx.y * 128;
    const int wid  = t >> 5, lane = t & 31;
    const int wm   = wid >> 2, wn = wid & 3;    // 2 x 4 warp grid
    const int g    = lane >> 2, tt = lane & 3;

    const int r  = t >> 1;             // tile row 0..127
    const int kq = (t & 1) * 16;       // k-half in fp16 elements

    float c[4][4][4];
    #pragma unroll
    for (int i = 0; i < 4; i++)
        #pragma unroll
        for (int j = 0; j < 4; j++)
            #pragma unroll
            for (int k = 0; k < 4; k++) c[i][j][k] = 0.0f;

    const int mid = lane >> 3;            // ldmatrix matrix id 0..3
    const uint32_t As_u = (uint32_t)__cvta_generic_to_shared(As);
    const uint32_t Bs_u = (uint32_t)__cvta_generic_to_shared(Bs);
    int a_off[4];
    #pragma unroll
    for (int fm = 0; fm < 4; fm++)
        a_off[fm] = (wm * 64 + fm * 16 + (mid & 1) * 8 + (lane & 7)) * SA + (mid >> 1) * 4;
    int b_off[2];
    #pragma unroll
    for (int p = 0; p < 2; p++)
        b_off[p] = (wn * 32 + p * 16 + (mid >> 1) * 8 + (lane & 7)) * SA + (mid & 1) * 4;

    const int am = min(m0 + r, N_NODES - 1);   // clamp (dup rows, masked at store)
    uint4 va0, va1, vb0, vb1;
    auto loadTile = [&](int k0) {
        // A: fp32 -> fp16 inline (convert immediately; 8-u32 live range)
        const float4* pa = (const float4*)(x + (size_t)am * IN_CH + k0 + kq);
        float4 a0 = pa[0], a1 = pa[1], a2 = pa[2], a3 = pa[3];
        va0.x = f2h2(a0.x, a0.y); va0.y = f2h2(a0.z, a0.w);
        va0.z = f2h2(a1.x, a1.y); va0.w = f2h2(a1.z, a1.w);
        va1.x = f2h2(a2.x, a2.y); va1.y = f2h2(a2.z, a2.w);
        va1.z = f2h2(a3.x, a3.y); va1.w = f2h2(a3.z, a3.w);
        // B: already fp16
        const uint4* pb = (const uint4*)&g_w16[(n0 + r) * IN_CH + k0 + kq];
        vb0 = pb[0]; vb1 = pb[1];
    };
    const int s_sts = r * SA + (kq >> 1);
    auto stsTile = [&](int buf) {
        int s = buf * BUFW + s_sts;
        *(uint4*)&As[s] = va0; *(uint4*)&As[s + 4] = va1;
        *(uint4*)&Bs[s] = vb0; *(uint4*)&Bs[s + 4] = vb1;
    };

    loadTile(0);
    stsTile(0);
    __syncthreads();

    #pragma unroll
    for (int it = 0; it < IN_CH / 32; it++) {
        const int buf = it & 1;
        const bool more = (it + 1) < IN_CH / 32;
        if (more) loadTile((it + 1) * 32);     // LDG overlaps this iter's MMA

        const uint32_t a_base = As_u + 4u * (uint32_t)(buf * BUFW);
        const uint32_t b_base = Bs_u + 4u * (uint32_t)(buf * BUFW);
        #pragma unroll
        for (int ks = 0; ks < 2; ks++) {
            const int kw = ks * 8;
            uint32_t bf[4][2];
            {
                uint32_t rr[4];
                ldsm_x4(rr, b_base + 4u * (b_off[0] + kw));
                bf[0][0] = rr[0]; bf[0][1] = rr[1]; bf[1][0] = rr[2]; bf[1][1] = rr[3];
                ldsm_x4(rr, b_base + 4u * (b_off[1] + kw));
                bf[2][0] = rr[0]; bf[2][1] = rr[1]; bf[3][0] = rr[2]; bf[3][1] = rr[3];
            }
            #pragma unroll
            for (int fm = 0; fm < 4; fm++) {
                uint32_t af[4];
                ldsm_x4(af, a_base + 4u * (a_off[fm] + kw));
                #pragma unroll
                for (int fn = 0; fn < 4; fn++)
                    mma_f16(c[fm][fn], af, bf[fn]);
            }
        }
        if (more) stsTile(buf ^ 1);            // write next buffer, then publish
        __syncthreads();
    }

    // ---- epilogue: store fp16 Wh + fused eL/eR ----
    const int h = blockIdx.y * 4 + wn;   // global head for this warp
    float aLv[8], aRv[8];
    #pragma unroll
    for (int fn = 0; fn < 4; fn++) {
        int c0 = fn * 8 + 2 * tt;
        aLv[2 * fn]     = aL[h * 32 + c0];
        aLv[2 * fn + 1] = aL[h * 32 + c0 + 1];
        aRv[2 * fn]     = aR[h * 32 + c0];
        aRv[2 * fn + 1] = aR[h * 32 + c0 + 1];
    }

    #pragma unroll
    for (int fm = 0; fm < 4; fm++) {
        int mrow = m0 + wm * 64 + fm * 16 + g;
        #pragma unroll
        for (int fn = 0; fn < 4; fn++) {
            int colp = (n0 + wn * 32 + fn * 8 + 2 * tt) >> 1;  // half2 index
            if (mrow < N_NODES)
                g_Whh[(size_t)mrow * (HC / 2) + colp] =
                    __floats2half2_rn(c[fm][fn][0], c[fm][fn][1]);
            if (mrow + 8 < N_NODES)
                g_Whh[(size_t)(mrow + 8) * (HC / 2) + colp] =
                    __floats2half2_rn(c[fm][fn][2], c[fm][fn][3]);
        }
        #pragma unroll
        for (int half = 0; half < 2; half++) {
            float pl = 0.f, pr = 0.f;
            #pragma unroll
            for (int fn = 0; fn < 4; fn++) {
                pl += c[fm][fn][2 * half] * aLv[2 * fn] + c[fm][fn][2 * half + 1] * aLv[2 * fn + 1];
                pr += c[fm][fn][2 * half] * aRv[2 * fn] + c[fm][fn][2 * half + 1] * aRv[2 * fn + 1];
            }
            pl += __shfl_xor_sync(0xffffffffu, pl, 1);
            pl += __shfl_xor_sync(0xffffffffu, pl, 2);
            pr += __shfl_xor_sync(0xffffffffu, pr, 1);
            pr += __shfl_xor_sync(0xffffffffu, pr, 2);
            int m = mrow + half * 8;
            if (tt == 0 && m < N_NODES) {
                g_eL[m * HEADS + h] = pl;
                g_eR[m * HEADS + h] = pr;
            }
        }
    }
}

// ---------------- degree count: 4 edges / thread ----------------
__global__ void deg_kernel(const void* __restrict__ ei) {
    int e4 = blockIdx.x * blockDim.x + threadIdx.x;
    if (e4 * 4 >= N_EDGES) return;
    int d[4];
    if (g_is64) {
        const longlong2* p = (const longlong2*)((const long long*)ei + N_EDGES) + e4 * 2;
        longlong2 v0 = p[0], v1 = p[1];
        d[0] = (int)v0.x; d[1] = (int)v0.y; d[2] = (int)v1.x; d[3] = (int)v1.y;
    } else {
        int4 v = ((const int4*)((const int*)ei + N_EDGES))[e4];
        d[0] = v.x; d[1] = v.y; d[2] = v.z; d[3] = v.w;
    }
    #pragma unroll
    for (int i = 0; i < 4; i++) atomicAdd(&g_deg[d[i]], 1);
}

// ---------------- scan phase 1: per-block sums ----------
__global__ __launch_bounds__(SCAN_CHUNK)
void scan1_kernel() {
    __shared__ int wsum[SCAN_CHUNK / 32];
    int t = threadIdx.x, lane = t & 31, w = t >> 5;
    int idx = blockIdx.x * SCAN_CHUNK + t;
    int v = (idx < N_NODES) ? g_deg[idx] : 0;
    #pragma unroll
    for (int off = 16; off > 0; off >>= 1) v += __shfl_down_sync(0xffffffffu, v, off);
    if (lane == 0) wsum[w] = v;
    __syncthreads();
    if (t < SCAN_CHUNK / 32) {
        int s = wsum[t];
        #pragma unroll
        for (int off = 8; off > 0; off >>= 1) s += __shfl_down_sync(0xffffu, s, off);
        if (t == 0) g_blocksum[blockIdx.x] = s;
    }
}

// ---------------- scan phase 3: block-local scan + inline block offset ----
__global__ __launch_bounds__(SCAN_CHUNK)
void scan3_kernel() {
    __shared__ int wsum[SCAN_CHUNK / 32];
    __shared__ int s_boff;
    int t = threadIdx.x, lane = t & 31, w = t >> 5;

    if (w == 0) {
        int s = 0;
        for (int j = lane; j < blockIdx.x; j += 32) s += g_blocksum[j];
        #pragma unroll
        for (int off = 16; off > 0; off >>= 1) s += __shfl_down_sync(0xffffffffu, s, off);
        if (lane == 0) s_boff = s;
    }

    int idx = blockIdx.x * SCAN_CHUNK + t;
    int v = (idx < N_NODES) ? g_deg[idx] : 0;
    int incl = v;
    #pragma unroll
    for (int off = 1; off < 32; off <<= 1) {
        int nb = __shfl_up_sync(0xffffffffu, incl, off);
        if (lane >= off) incl += nb;
    }
    if (lane == 31) wsum[w] = incl;
    __syncthreads();
    if (t < SCAN_CHUNK / 32) {
        int s = wsum[t];
        #pragma unroll
        for (int off = 1; off < SCAN_CHUNK / 32; off <<= 1) {
            int nb = __shfl_up_sync(0xffffu, s, off);
            if ((t & 15) >= off) s += nb;
        }
        wsum[t] = s;
    }
    __syncthreads();
    int incl_tot = incl + (w ? wsum[w - 1] : 0) + s_boff;
    if (idx < N_NODES) {
        g_cursor[idx]   = incl_tot - v;
        g_ptr[idx + 1]  = incl_tot;
    }
    if (idx == 0) g_ptr[0] = 0;
}

// ---------------- CSR fill: 4 edges / thread ----------------
__global__ void scatter_kernel(const void* __restrict__ ei) {
    int e4 = blockIdx.x * blockDim.x + threadIdx.x;
    if (e4 * 4 >= N_EDGES) return;
    int s[4], d[4];
    if (g_is64) {
        const longlong2* ps = (const longlong2*)ei + e4 * 2;
        const longlong2* pd = (const longlong2*)((const long long*)ei + N_EDGES) + e4 * 2;
        longlong2 s0 = ps[0], s1 = ps[1], d0 = pd[0], d1 = pd[1];
        s[0] = (int)s0.x; s[1] = (int)s0.y; s[2] = (int)s1.x; s[3] = (int)s1.y;
        d[0] = (int)d0.x; d[1] = (int)d0.y; d[2] = (int)d1.x; d[3] = (int)d1.y;
    } else {
        int4 vs = ((const int4*)ei)[e4];
        int4 vd = ((const int4*)((const int*)ei + N_EDGES))[e4];
        s[0] = vs.x; s[1] = vs.y; s[2] = vs.z; s[3] = vs.w;
        d[0] = vd.x; d[1] = vd.y; d[2] = vd.z; d[3] = vd.w;
    }
    #pragma unroll
    for (int i = 0; i < 4; i++) {
        int pos = atomicAdd(&g_cursor[d[i]], 1);
        g_csr_src[pos] = s[i];
    }
}

// ---------------- aggregation: warp-per-node, prefetched FMA loop --------
__device__ __forceinline__ void fma_row(float* acc, float w, uint4 v) {
    float2 f0 = __half22float2(*reinterpret_cast<const __half2*>(&v.x));
    float2 f1 = __half22float2(*reinterpret_cast<const __half2*>(&v.y));
    float2 f2 = __half22float2(*reinterpret_cast<const __half2*>(&v.z));
    float2 f3 = __half22float2(*reinterpret_cast<const __half2*>(&v.w));
    acc[0] = fmaf(w, f0.x, acc[0]); acc[1] = fmaf(w, f0.y, acc[1]);
    acc[2] = fmaf(w, f1.x, acc[2]); acc[3] = fmaf(w, f1.y, acc[3]);
    acc[4] = fmaf(w, f2.x, acc[4]); acc[5] = fmaf(w, f2.y, acc[5]);
    acc[6] = fmaf(w, f3.x, acc[6]); acc[7] = fmaf(w, f3.y, acc[7]);
}

__global__ __launch_bounds__(256)
void agg_kernel(float* __restrict__ out) {
    __shared__ float s_w[8][32][9];   // [warp][edge][head], stride 9: conflict-free

    const int lane = threadIdx.x & 31;
    const int wix  = threadIdx.x >> 5;            // warp in block
    const int n = blockIdx.x * 8 + wix;
    if (n >= N_NODES) return;

    const int hq = lane >> 2;                     // head for FMA phase (channels)

    float er[8];
    {
        float4 r0 = *(const float4*)&g_eR[n * HEADS];
        float4 r1 = *(const float4*)&g_eR[n * HEADS + 4];
        er[0] = r0.x; er[1] = r0.y; er[2] = r0.z; er[3] = r0.w;
        er[4] = r1.x; er[5] = r1.y; er[6] = r1.z; er[7] = r1.w;
    }

    float acc[8];
    float denom;
    {
        float4 l0 = *(const float4*)&g_eL[n * HEADS];
        float4 l1 = *(const float4*)&g_eL[n * HEADS + 4];
        float el[8] = {l0.x, l0.y, l0.z, l0.w, l1.x, l1.y, l1.z, l1.w};
        float s = el[hq] + er[hq];
        s = fmaxf(s, NEG_SLOPE * s);
        float wself = __expf(s);
        uint4 v = ((const uint4*)&g_Whh[(size_t)n * (HC / 2)])[lane];
        float2 f0 = __half22float2(*reinterpret_cast<const __half2*>(&v.x));
        float2 f1 = __half22float2(*reinterpret_cast<const __half2*>(&v.y));
        float2 f2 = __half22float2(*reinterpret_cast<const __half2*>(&v.z));
        float2 f3 = __half22float2(*reinterpret_cast<const __half2*>(&v.w));
        acc[0] = wself * f0.x; acc[1] = wself * f0.y;
        acc[2] = wself * f1.x; acc[3] = wself * f1.y;
        acc[4] = wself * f2.x; acc[5] = wself * f2.y;
        acc[6] = wself * f3.x; acc[7] = wself * f3.y;
        denom = wself;
    }

    const int beg = g_ptr[n];
    const int end = g_ptr[n + 1];

    for (int base = beg; base < end; base += 32) {
        int cnt = min(32, end - base);
        int src_l = 0;
        if (lane < cnt) {
            src_l = g_csr_src[base + lane];
            float4 l0 = *(const float4*)&g_eL[src_l * HEADS];
            float4 l1 = *(const float4*)&g_eL[src_l * HEADS + 4];
            float el[8] = {l0.x, l0.y, l0.z, l0.w, l1.x, l1.y, l1.z, l1.w};
            #pragma unroll
            for (int h = 0; h < 8; h++) {
                float s = el[h] + er[h];
                s = fmaxf(s, NEG_SLOPE * s);
                s_w[wix][lane][h] = __expf(s);
            }
        }
        __syncwarp();

        // prefetched FMA loop: next edge's Wh load issues before current FMAs
        int src0 = __shfl_sync(0xffffffffu, src_l, 0);
        uint4 v = ((const uint4*)&g_Whh[(size_t)src0 * (HC / 2)])[lane];
        for (int k = 0; k < cnt; k++) {
            uint4 vn;
            if (k + 1 < cnt) {
                int srcn = __shfl_sync(0xffffffffu, src_l, k + 1);
                vn = ((const uint4*)&g_Whh[(size_t)srcn * (HC / 2)])[lane];
            }
            float w = s_w[wix][k][hq];
            fma_row(acc, w, v);
            denom += w;
            v = vn;
        }
        __syncwarp();
    }

    float inv = 1.0f / (denom + 1e-16f);
    float* op = out + (size_t)n * HC + lane * 8;
    *(float4*)op       = make_float4(acc[0] * inv, acc[1] * inv, acc[2] * inv, acc[3] * inv);
    *(float4*)(op + 4) = make_float4(acc[4] * inv, acc[5] * inv, acc[6] * inv, acc[7] * inv);
}

// ---------------- launch: forked-capture dual stream ----------------
extern "C" void kernel_launch(void* const* d_in, const int* in_sizes, int n_in,
                              void* d_out, int out_size) {
    const float* x  = (const float*)d_in[0];
    const void*  ei = (const void*)d_in[1];
    const float* W  = (const float*)d_in[2];
    const float* aL = (const float*)d_in[3];
    const float* aR = (const float*)d_in[4];
    float* out = (float*)d_out;

    cudaStream_t s2;
    cudaStreamCreateWithFlags(&s2, cudaStreamNonBlocking);
    cudaEvent_t eFork, eJoin;
    cudaEventCreateWithFlags(&eFork, cudaEventDisableTiming);
    cudaEventCreateWithFlags(&eJoin, cudaEventDisableTiming);

    // fork: edge-prep chain on s2, gemm chain on default stream
    cudaEventRecord(eFork, 0);
    cudaStreamWaitEvent(s2, eFork, 0);

    cvt_w_kernel<<<(W_CVT_THREADS + 255) / 256, 256>>>(W);                          // 0 (s0)
    init_edge_kernel<<<(N_NODES + 255) / 256, 256, 0, s2>>>((const int*)ei);        // 1 (s2)
    deg_kernel<<<(N_EDGES / 4 + 255) / 256, 256, 0, s2>>>(ei);                      // 2 (s2)

    dim3 ggrid((N_NODES + 127) / 128, HC / 128);
    gemm_kernel<<<ggrid, 256>>>(x, aL, aR);                                         // 3 (s0) <- profiled

    scan1_kernel<<<SCAN_BLOCKS, SCAN_CHUNK, 0, s2>>>();                             // 4 (s2)
    scan3_kernel<<<SCAN_BLOCKS, SCAN_CHUNK, 0, s2>>>();                             // 5 (s2)
    scatter_kernel<<<(N_EDGES / 4 + 255) / 256, 256, 0, s2>>>(ei);                  // 6 (s2)
    cudaEventRecord(eJoin, s2);

    // join: agg needs CSR (s2) + Wh/eL/eR (s0)
    cudaStreamWaitEvent(0, eJoin, 0);
    agg_kernel<<<(N_NODES + 7) / 8, 256>>>(out);                                    // 7 (s0)

    cudaEventDestroy(eFork);
    cudaEventDestroy(eJoin);
    cudaStreamDestroy(s2);
}

// round 14
// speedup vs baseline: 1.5572x; 1.5572x over previous
#include <cuda_runtime.h>
#include <cuda_bf16.h>
#include <cuda_fp16.h>
#include <cstdint>

// ---------------- problem constants ----------------
#define N_NODES   50000
#define N_EDGES   800000
#define IN_CH     256
#define HEADS     8
#define OUT_CH    32
#define HC        256          // HEADS*OUT_CH
#define NEG_SLOPE 0.2f

#define SCAN_CHUNK  512
#define SCAN_BLOCKS ((N_NODES + SCAN_CHUNK - 1) / SCAN_CHUNK)   // 98

// ---------------- device scratch ----------------
__device__ __half2 g_Whh[(size_t)N_NODES * (HC / 2)];    // 25.6 MB fp16 Wh
__device__ ushort  g_x16[(size_t)N_NODES * IN_CH];       // 25.6 MB fp16 x
__device__ ushort  g_w16[HC * IN_CH];                    // 128 KB fp16 W
__device__ float g_eL[N_NODES * HEADS];
__device__ float g_eR[N_NODES * HEADS];
__device__ int   g_deg[N_NODES];
__device__ int   g_ptr[N_NODES + 1];
__device__ int   g_cursor[N_NODES];
__device__ int   g_csr_src[N_EDGES];
__device__ int   g_blocksum[SCAN_BLOCKS];
__device__ int   g_is64;

#define X_CVT_THREADS (N_NODES * IN_CH / 8)   // 1,600,000
#define W_CVT_THREADS (HC * IN_CH / 8)        // 8,192
#define CVT_THREADS   (X_CVT_THREADS + W_CVT_THREADS)

// ---------------- fp16 conversion of x, W (stream 0, feeds gemm) ---------
__device__ __forceinline__ void cvt8(const float* src, ushort* dst) {
    float4 a = *(const float4*)src;
    float4 b = *(const float4*)(src + 4);
    __half2 h[4];
    h[0] = __floats2half2_rn(a.x, a.y);
    h[1] = __floats2half2_rn(a.z, a.w);
    h[2] = __floats2half2_rn(b.x, b.y);
    h[3] = __floats2half2_rn(b.z, b.w);
    *(uint4*)dst = *(uint4*)h;
}

__global__ void cvt_kernel(const float* __restrict__ x, const float* __restrict__ W) {
    int i = blockIdx.x * blockDim.x + threadIdx.x;
    if (i < X_CVT_THREADS) {
        size_t off = (size_t)i * 8;
        cvt8(x + off, g_x16 + off);
    } else if (i < CVT_THREADS) {
        size_t off = (size_t)(i - X_CVT_THREADS) * 8;
        cvt8(W + off, g_w16 + off);
    }
}

// ---------------- edge-chain init: detect dtype + zero deg (stream 2) ----
__global__ void init_edge_kernel(const int* ei_words) {
    int i = blockIdx.x * blockDim.x + threadIdx.x;
    if (i == 0) {
        int all0 = 1;
        for (int k = 0; k < 64; k++) {
            if (ei_words[2 * k + 1] != 0) { all0 = 0; break; }
        }
        g_is64 = all0;
    }
    if (i < N_NODES) g_deg[i] = 0;
}

// ---------------- tensor-core primitives ----------------
__device__ __forceinline__ void mma_f16(float* c, const uint32_t* a, const uint32_t* b) {
    asm volatile(
        "mma.sync.aligned.m16n8k16.row.col.f32.f16.f16.f32 "
        "{%0,%1,%2,%3}, {%4,%5,%6,%7}, {%8,%9}, {%0,%1,%2,%3};\n"
        : "+f"(c[0]), "+f"(c[1]), "+f"(c[2]), "+f"(c[3])
        : "r"(a[0]), "r"(a[1]), "r"(a[2]), "r"(a[3]), "r"(b[0]), "r"(b[1]));
}

__device__ __forceinline__ void ldsm_x4(uint32_t* r, uint32_t addr) {
    asm volatile("ldmatrix.sync.aligned.m8n8.x4.shared.b16 {%0,%1,%2,%3}, [%4];"
        : "=r"(r[0]), "=r"(r[1]), "=r"(r[2]), "=r"(r[3]) : "r"(addr));
}

// ---------------- GEMM: Wh = x @ W^T  (fp16 MMA + ldmatrix, 2-stage) -----
// Tile: BM=128, BN=128, BK=32. 8 warps (2x4). Warp tile 64x32 = one head.
#define SA 20          // smem row stride in uint32 (40 fp16 = 80B, LDSM conflict-free)
#define BUFW (128 * SA)

__global__ __launch_bounds__(256, 2)
void gemm_kernel(const float* __restrict__ aL, const float* __restrict__ aR) {
    __shared__ uint32_t As[2 * BUFW];
    __shared__ uint32_t Bs[2 * BUFW];

    const int t    = threadIdx.x;
    const int m0   = blockIdx.x * 128;
    const int n0   = blockIdx.y * 128;
    const int wid  = t >> 5, lane = t & 31;
    const int wm   = wid >> 2, wn = wid & 3;    // 2 x 4 warp grid
    const int g    = lane >> 2, tt = lane & 3;

    const int r  = t >> 1;             // tile row 0..127
    const int kq = (t & 1) * 16;       // k-half in fp16 elements

    float c[4][4][4];
    #pragma unroll
    for (int i = 0; i < 4; i++)
        #pragma unroll
        for (int j = 0; j < 4; j++)
            #pragma unroll
            for (int k = 0; k < 4; k++) c[i][j][k] = 0.0f;

    const int mid = lane >> 3;            // ldmatrix matrix id 0..3
    const uint32_t As_u = (uint32_t)__cvta_generic_to_shared(As);
    const uint32_t Bs_u = (uint32_t)__cvta_generic_to_shared(Bs);
    int a_off[4];
    #pragma unroll
    for (int fm = 0; fm < 4; fm++)
        a_off[fm] = (wm * 64 + fm * 16 + (mid & 1) * 8 + (lane & 7)) * SA + (mid >> 1) * 4;
    int b_off[2];
    #pragma unroll
    for (int p = 0; p < 2; p++)
        b_off[p] = (wn * 32 + p * 16 + (mid >> 1) * 8 + (lane & 7)) * SA + (mid & 1) * 4;

    const int am = min(m0 + r, N_NODES - 1);   // clamp (dup rows, masked at store)
    uint4 va0, va1, vb0, vb1;
    auto loadTile = [&](int k0) {
        const uint4* pa = (const uint4*)&g_x16[(size_t)am * IN_CH + k0 + kq];
        va0 = pa[0]; va1 = pa[1];
        const uint4* pb = (const uint4*)&g_w16[(n0 + r) * IN_CH + k0 + kq];
        vb0 = pb[0]; vb1 = pb[1];
    };
    const int s_sts = r * SA + (kq >> 1);
    auto stsTile = [&](int buf) {
        int s = buf * BUFW + s_sts;
        *(uint4*)&As[s] = va0; *(uint4*)&As[s + 4] = va1;
        *(uint4*)&Bs[s] = vb0; *(uint4*)&Bs[s + 4] = vb1;
    };

    loadTile(0);
    stsTile(0);
    __syncthreads();

    #pragma unroll
    for (int it = 0; it < IN_CH / 32; it++) {
        const int buf = it & 1;
        const bool more = (it + 1) < IN_CH / 32;
        if (more) loadTile((it + 1) * 32);     // LDG overlaps this iter's MMA

        const uint32_t a_base = As_u + 4u * (uint32_t)(buf * BUFW);
        const uint32_t b_base = Bs_u + 4u * (uint32_t)(buf * BUFW);
        #pragma unroll
        for (int ks = 0; ks < 2; ks++) {
            const int kw = ks * 8;
            uint32_t bf[4][2];
            {
                uint32_t rr[4];
                ldsm_x4(rr, b_base + 4u * (b_off[0] + kw));
                bf[0][0] = rr[0]; bf[0][1] = rr[1]; bf[1][0] = rr[2]; bf[1][1] = rr[3];
                ldsm_x4(rr, b_base + 4u * (b_off[1] + kw));
                bf[2][0] = rr[0]; bf[2][1] = rr[1]; bf[3][0] = rr[2]; bf[3][1] = rr[3];
            }
            #pragma unroll
            for (int fm = 0; fm < 4; fm++) {
                uint32_t af[4];
                ldsm_x4(af, a_base + 4u * (a_off[fm] + kw));
                #pragma unroll
                for (int fn = 0; fn < 4; fn++)
                    mma_f16(c[fm][fn], af, bf[fn]);
            }
        }
        if (more) stsTile(buf ^ 1);            // write next buffer, then publish
        __syncthreads();
    }

    // ---- epilogue: store fp16 Wh + fused eL/eR ----
    const int h = blockIdx.y * 4 + wn;   // global head for this warp
    float aLv[8], aRv[8];
    #pragma unroll
    for (int fn = 0; fn < 4; fn++) {
        int c0 = fn * 8 + 2 * tt;
        aLv[2 * fn]     = aL[h * 32 + c0];
        aLv[2 * fn + 1] = aL[h * 32 + c0 + 1];
        aRv[2 * fn]     = aR[h * 32 + c0];
        aRv[2 * fn + 1] = aR[h * 32 + c0 + 1];
    }

    #pragma unroll
    for (int fm = 0; fm < 4; fm++) {
        int mrow = m0 + wm * 64 + fm * 16 + g;
        #pragma unroll
        for (int fn = 0; fn < 4; fn++) {
            int colp = (n0 + wn * 32 + fn * 8 + 2 * tt) >> 1;  // half2 index
            if (mrow < N_NODES)
                g_Whh[(size_t)mrow * (HC / 2) + colp] =
                    __floats2half2_rn(c[fm][fn][0], c[fm][fn][1]);
            if (mrow + 8 < N_NODES)
                g_Whh[(size_t)(mrow + 8) * (HC / 2) + colp] =
                    __floats2half2_rn(c[fm][fn][2], c[fm][fn][3]);
        }
        #pragma unroll
        for (int half = 0; half < 2; half++) {
            float pl = 0.f, pr = 0.f;
            #pragma unroll
            for (int fn = 0; fn < 4; fn++) {
                pl += c[fm][fn][2 * half] * aLv[2 * fn] + c[fm][fn][2 * half + 1] * aLv[2 * fn + 1];
                pr += c[fm][fn][2 * half] * aRv[2 * fn] + c[fm][fn][2 * half + 1] * aRv[2 * fn + 1];
            }
            pl += __shfl_xor_sync(0xffffffffu, pl, 1);
            pl += __shfl_xor_sync(0xffffffffu, pl, 2);
            pr += __shfl_xor_sync(0xffffffffu, pr, 1);
            pr += __shfl_xor_sync(0xffffffffu, pr, 2);
            int m = mrow + half * 8;
            if (tt == 0 && m < N_NODES) {
                g_eL[m * HEADS + h] = pl;
                g_eR[m * HEADS + h] = pr;
            }
        }
    }
}

// ---------------- degree count: 4 edges / thread ----------------
__global__ void deg_kernel(const void* __restrict__ ei) {
    int e4 = blockIdx.x * blockDim.x + threadIdx.x;
    if (e4 * 4 >= N_EDGES) return;
    int d[4];
    if (g_is64) {
        const longlong2* p = (const longlong2*)((const long long*)ei + N_EDGES) + e4 * 2;
        longlong2 v0 = p[0], v1 = p[1];
        d[0] = (int)v0.x; d[1] = (int)v0.y; d[2] = (int)v1.x; d[3] = (int)v1.y;
    } else {
        int4 v = ((const int4*)((const int*)ei + N_EDGES))[e4];
        d[0] = v.x; d[1] = v.y; d[2] = v.z; d[3] = v.w;
    }
    #pragma unroll
    for (int i = 0; i < 4; i++) atomicAdd(&g_deg[d[i]], 1);
}

// ---------------- scan phase 1: per-block sums ----------
__global__ __launch_bounds__(SCAN_CHUNK)
void scan1_kernel() {
    __shared__ int wsum[SCAN_CHUNK / 32];
    int t = threadIdx.x, lane = t & 31, w = t >> 5;
    int idx = blockIdx.x * SCAN_CHUNK + t;
    int v = (idx < N_NODES) ? g_deg[idx] : 0;
    #pragma unroll
    for (int off = 16; off > 0; off >>= 1) v += __shfl_down_sync(0xffffffffu, v, off);
    if (lane == 0) wsum[w] = v;
    __syncthreads();
    if (t < SCAN_CHUNK / 32) {
        int s = wsum[t];
        #pragma unroll
        for (int off = 8; off > 0; off >>= 1) s += __shfl_down_sync(0xffffu, s, off);
        if (t == 0) g_blocksum[blockIdx.x] = s;
    }
}

// ---------------- scan phase 3: block-local scan + inline block offset ----
__global__ __launch_bounds__(SCAN_CHUNK)
void scan3_kernel() {
    __shared__ int wsum[SCAN_CHUNK / 32];
    __shared__ int s_boff;
    int t = threadIdx.x, lane = t & 31, w = t >> 5;

    if (w == 0) {
        int s = 0;
        for (int j = lane; j < blockIdx.x; j += 32) s += g_blocksum[j];
        #pragma unroll
        for (int off = 16; off > 0; off >>= 1) s += __shfl_down_sync(0xffffffffu, s, off);
        if (lane == 0) s_boff = s;
    }

    int idx = blockIdx.x * SCAN_CHUNK + t;
    int v = (idx < N_NODES) ? g_deg[idx] : 0;
    int incl = v;
    #pragma unroll
    for (int off = 1; off < 32; off <<= 1) {
        int nb = __shfl_up_sync(0xffffffffu, incl, off);
        if (lane >= off) incl += nb;
    }
    if (lane == 31) wsum[w] = incl;
    __syncthreads();
    if (t < SCAN_CHUNK / 32) {
        int s = wsum[t];
        #pragma unroll
        for (int off = 1; off < SCAN_CHUNK / 32; off <<= 1) {
            int nb = __shfl_up_sync(0xffffu, s, off);
            if ((t & 15) >= off) s += nb;
        }
        wsum[t] = s;
    }
    __syncthreads();
    int incl_tot = incl + (w ? wsum[w - 1] : 0) + s_boff;
    if (idx < N_NODES) {
        g_cursor[idx]   = incl_tot - v;
        g_ptr[idx + 1]  = incl_tot;
    }
    if (idx == 0) g_ptr[0] = 0;
}

// ---------------- CSR fill: 4 edges / thread ----------------
__global__ void scatter_kernel(const void* __restrict__ ei) {
    int e4 = blockIdx.x * blockDim.x + threadIdx.x;
    if (e4 * 4 >= N_EDGES) return;
    int s[4], d[4];
    if (g_is64) {
        const longlong2* ps = (const longlong2*)ei + e4 * 2;
        const longlong2* pd = (const longlong2*)((const long long*)ei + N_EDGES) + e4 * 2;
        longlong2 s0 = ps[0], s1 = ps[1], d0 = pd[0], d1 = pd[1];
        s[0] = (int)s0.x; s[1] = (int)s0.y; s[2] = (int)s1.x; s[3] = (int)s1.y;
        d[0] = (int)d0.x; d[1] = (int)d0.y; d[2] = (int)d1.x; d[3] = (int)d1.y;
    } else {
        int4 vs = ((const int4*)ei)[e4];
        int4 vd = ((const int4*)((const int*)ei + N_EDGES))[e4];
        s[0] = vs.x; s[1] = vs.y; s[2] = vs.z; s[3] = vs.w;
        d[0] = vd.x; d[1] = vd.y; d[2] = vd.z; d[3] = vd.w;
    }
    #pragma unroll
    for (int i = 0; i < 4; i++) {
        int pos = atomicAdd(&g_cursor[d[i]], 1);
        g_csr_src[pos] = s[i];
    }
}

// ---------------- aggregation: warp-per-node, batched 4-wide FMA loop ----
__device__ __forceinline__ void fma_row(float* acc, float w, uint4 v) {
    float2 f0 = __half22float2(*reinterpret_cast<const __half2*>(&v.x));
    float2 f1 = __half22float2(*reinterpret_cast<const __half2*>(&v.y));
    float2 f2 = __half22float2(*reinterpret_cast<const __half2*>(&v.z));
    float2 f3 = __half22float2(*reinterpret_cast<const __half2*>(&v.w));
    acc[0] = fmaf(w, f0.x, acc[0]); acc[1] = fmaf(w, f0.y, acc[1]);
    acc[2] = fmaf(w, f1.x, acc[2]); acc[3] = fmaf(w, f1.y, acc[3]);
    acc[4] = fmaf(w, f2.x, acc[4]); acc[5] = fmaf(w, f2.y, acc[5]);
    acc[6] = fmaf(w, f3.x, acc[6]); acc[7] = fmaf(w, f3.y, acc[7]);
}

__global__ __launch_bounds__(256)
void agg_kernel(float* __restrict__ out) {
    __shared__ float s_w[8][32][9];   // [warp][edge][head], stride 9: conflict-free

    const int lane = threadIdx.x & 31;
    const int wix  = threadIdx.x >> 5;            // warp in block
    const int n = blockIdx.x * 8 + wix;
    if (n >= N_NODES) return;

    const int hq = lane >> 2;                     // head for FMA phase (channels)

    float er[8];
    {
        float4 r0 = *(const float4*)&g_eR[n * HEADS];
        float4 r1 = *(const float4*)&g_eR[n * HEADS + 4];
        er[0] = r0.x; er[1] = r0.y; er[2] = r0.z; er[3] = r0.w;
        er[4] = r1.x; er[5] = r1.y; er[6] = r1.z; er[7] = r1.w;
    }

    float acc[8];
    float denom;
    {
        float4 l0 = *(const float4*)&g_eL[n * HEADS];
        float4 l1 = *(const float4*)&g_eL[n * HEADS + 4];
        float el[8] = {l0.x, l0.y, l0.z, l0.w, l1.x, l1.y, l1.z, l1.w};
        float s = el[hq] + er[hq];
        s = fmaxf(s, NEG_SLOPE * s);
        float wself = __expf(s);
        uint4 v = ((const uint4*)&g_Whh[(size_t)n * (HC / 2)])[lane];
        float2 f0 = __half22float2(*reinterpret_cast<const __half2*>(&v.x));
        float2 f1 = __half22float2(*reinterpret_cast<const __half2*>(&v.y));
        float2 f2 = __half22float2(*reinterpret_cast<const __half2*>(&v.z));
        float2 f3 = __half22float2(*reinterpret_cast<const __half2*>(&v.w));
        acc[0] = wself * f0.x; acc[1] = wself * f0.y;
        acc[2] = wself * f1.x; acc[3] = wself * f1.y;
        acc[4] = wself * f2.x; acc[5] = wself * f2.y;
        acc[6] = wself * f3.x; acc[7] = wself * f3.y;
        denom = wself;
    }

    const int beg = g_ptr[n];
    const int end = g_ptr[n + 1];

    for (int base = beg; base < end; base += 32) {
        int cnt = min(32, end - base);
        int src_l = 0;
        if (lane < cnt) {
            src_l = g_csr_src[base + lane];
            float4 l0 = *(const float4*)&g_eL[src_l * HEADS];
            float4 l1 = *(const float4*)&g_eL[src_l * HEADS + 4];
            float el[8] = {l0.x, l0.y, l0.z, l0.w, l1.x, l1.y, l1.z, l1.w};
            #pragma unroll
            for (int h = 0; h < 8; h++) {
                float s = el[h] + er[h];
                s = fmaxf(s, NEG_SLOPE * s);
                s_w[wix][lane][h] = __expf(s);
            }
        }
        __syncwarp();

        // branch-free 4-wide batched loads: 4 independent LDGs in flight
        int k = 0;
        for (; k + 4 <= cnt; k += 4) {
            int s0 = __shfl_sync(0xffffffffu, src_l, k);
            int s1 = __shfl_sync(0xffffffffu, src_l, k + 1);
            int s2 = __shfl_sync(0xffffffffu, src_l, k + 2);
            int s3 = __shfl_sync(0xffffffffu, src_l, k + 3);
            uint4 v0 = ((const uint4*)&g_Whh[(size_t)s0 * (HC / 2)])[lane];
            uint4 v1 = ((const uint4*)&g_Whh[(size_t)s1 * (HC / 2)])[lane];
            uint4 v2 = ((const uint4*)&g_Whh[(size_t)s2 * (HC / 2)])[lane];
            uint4 v3 = ((const uint4*)&g_Whh[(size_t)s3 * (HC / 2)])[lane];
            float w0 = s_w[wix][k][hq];
            float w1 = s_w[wix][k + 1][hq];
            float w2 = s_w[wix][k + 2][hq];
            float w3 = s_w[wix][k + 3][hq];
            fma_row(acc, w0, v0); denom += w0;
            fma_row(acc, w1, v1); denom += w1;
            fma_row(acc, w2, v2); denom += w2;
            fma_row(acc, w3, v3); denom += w3;
        }
        for (; k < cnt; k++) {
            int src = __shfl_sync(0xffffffffu, src_l, k);
            float w = s_w[wix][k][hq];
            uint4 v = ((const uint4*)&g_Whh[(size_t)src * (HC / 2)])[lane];
            fma_row(acc, w, v);
            denom += w;
        }
        __syncwarp();
    }

    float inv = 1.0f / (denom + 1e-16f);
    float* op = out + (size_t)n * HC + lane * 8;
    *(float4*)op       = make_float4(acc[0] * inv, acc[1] * inv, acc[2] * inv, acc[3] * inv);
    *(float4*)(op + 4) = make_float4(acc[4] * inv, acc[5] * inv, acc[6] * inv, acc[7] * inv);
}

// ---------------- launch: forked-capture dual stream ----------------
extern "C" void kernel_launch(void* const* d_in, const int* in_sizes, int n_in,
                              void* d_out, int out_size) {
    const float* x  = (const float*)d_in[0];
    const void*  ei = (const void*)d_in[1];
    const float* W  = (const float*)d_in[2];
    const float* aL = (const float*)d_in[3];
    const float* aR = (const float*)d_in[4];
    float* out = (float*)d_out;

    cudaStream_t s2;
    cudaStreamCreateWithFlags(&s2, cudaStreamNonBlocking);
    cudaEvent_t eFork, eJoin;
    cudaEventCreateWithFlags(&eFork, cudaEventDisableTiming);
    cudaEventCreateWithFlags(&eJoin, cudaEventDisableTiming);

    // fork: edge-prep chain on s2, gemm chain on default stream
    cudaEventRecord(eFork, 0);
    cudaStreamWaitEvent(s2, eFork, 0);

    cvt_kernel<<<(CVT_THREADS + 255) / 256, 256>>>(x, W);                           // 0 (s0)
    init_edge_kernel<<<(N_NODES + 255) / 256, 256, 0, s2>>>((const int*)ei);        // 1 (s2)
    deg_kernel<<<(N_EDGES / 4 + 255) / 256, 256, 0, s2>>>(ei);                      // 2 (s2)

    dim3 ggrid((N_NODES + 127) / 128, HC / 128);
    gemm_kernel<<<ggrid, 256>>>(aL, aR);                                            // 3 (s0) <- profiled

    scan1_kernel<<<SCAN_BLOCKS, SCAN_CHUNK, 0, s2>>>();                             // 4 (s2)
    scan3_kernel<<<SCAN_BLOCKS, SCAN_CHUNK, 0, s2>>>();                             // 5 (s2)
    scatter_kernel<<<(N_EDGES / 4 + 255) / 256, 256, 0, s2>>>(ei);                  // 6 (s2)
    cudaEventRecord(eJoin, s2);

    // join: agg needs CSR (s2) + Wh/eL/eR (s0)
    cudaStreamWaitEvent(0, eJoin, 0);
    agg_kernel<<<(N_NODES + 7) / 8, 256>>>(out);                                    // 7 (s0)

    cudaEventDestroy(eFork);
    cudaEventDestroy(eJoin);
    cudaStreamDestroy(s2);
}

// round 15
// speedup vs baseline: 1.5736x; 1.0106x over previous
#include <cuda_runtime.h>
#include <cuda_bf16.h>
#include <cuda_fp16.h>
#include <cstdint>

// ---------------- problem constants ----------------
#define N_NODES   50000
#define N_EDGES   800000
#define IN_CH     256
#define HEADS     8
#define OUT_CH    32
#define HC        256          // HEADS*OUT_CH
#define NEG_SLOPE 0.2f

#define SCAN_CHUNK  512
#define SCAN_BLOCKS ((N_NODES + SCAN_CHUNK - 1) / SCAN_CHUNK)   // 98

// ---------------- device scratch ----------------
__device__ __half2 g_Whh[(size_t)N_NODES * (HC / 2)];    // 25.6 MB fp16 Wh
__device__ ushort  g_x16[(size_t)N_NODES * IN_CH];       // 25.6 MB fp16 x
__device__ ushort  g_w16[HC * IN_CH];                    // 128 KB fp16 W
__device__ float g_eL[N_NODES * HEADS];
__device__ float g_eR[N_NODES * HEADS];
__device__ int   g_deg[N_NODES];
__device__ int   g_ptr[N_NODES + 1];
__device__ int   g_cursor[N_NODES];
__device__ int   g_csr_src[N_EDGES];
__device__ int   g_blocksum[SCAN_BLOCKS];
__device__ int   g_is64;

#define X_CVT_THREADS (N_NODES * IN_CH / 8)   // 1,600,000
#define W_CVT_THREADS (HC * IN_CH / 8)        // 8,192
#define CVT_THREADS   (X_CVT_THREADS + W_CVT_THREADS)

// ---------------- fp16 conversion of x, W (stream 0, feeds gemm) ---------
__device__ __forceinline__ void cvt8(const float* src, ushort* dst) {
    float4 a = *(const float4*)src;
    float4 b = *(const float4*)(src + 4);
    __half2 h[4];
    h[0] = __floats2half2_rn(a.x, a.y);
    h[1] = __floats2half2_rn(a.z, a.w);
    h[2] = __floats2half2_rn(b.x, b.y);
    h[3] = __floats2half2_rn(b.z, b.w);
    *(uint4*)dst = *(uint4*)h;
}

__global__ void cvt_kernel(const float* __restrict__ x, const float* __restrict__ W) {
    int i = blockIdx.x * blockDim.x + threadIdx.x;
    if (i < X_CVT_THREADS) {
        size_t off = (size_t)i * 8;
        cvt8(x + off, g_x16 + off);
    } else if (i < CVT_THREADS) {
        size_t off = (size_t)(i - X_CVT_THREADS) * 8;
        cvt8(W + off, g_w16 + off);
    }
}

// ---------------- edge-chain init: detect dtype + zero deg (stream 2) ----
__global__ void init_edge_kernel(const int* ei_words) {
    int i = blockIdx.x * blockDim.x + threadIdx.x;
    if (i == 0) {
        int all0 = 1;
        for (int k = 0; k < 64; k++) {
            if (ei_words[2 * k + 1] != 0) { all0 = 0; break; }
        }
        g_is64 = all0;
    }
    if (i < N_NODES) g_deg[i] = 0;
}

// ---------------- tensor-core primitives ----------------
__device__ __forceinline__ void mma_f16(float* c, const uint32_t* a, const uint32_t* b) {
    asm volatile(
        "mma.sync.aligned.m16n8k16.row.col.f32.f16.f16.f32 "
        "{%0,%1,%2,%3}, {%4,%5,%6,%7}, {%8,%9}, {%0,%1,%2,%3};\n"
        : "+f"(c[0]), "+f"(c[1]), "+f"(c[2]), "+f"(c[3])
        : "r"(a[0]), "r"(a[1]), "r"(a[2]), "r"(a[3]), "r"(b[0]), "r"(b[1]));
}

__device__ __forceinline__ void ldsm_x4(uint32_t* r, uint32_t addr) {
    asm volatile("ldmatrix.sync.aligned.m8n8.x4.shared.b16 {%0,%1,%2,%3}, [%4];"
        : "=r"(r[0]), "=r"(r[1]), "=r"(r[2]), "=r"(r[3]) : "r"(addr));
}

// ---------------- GEMM: Wh = x @ W^T  (fp16 MMA + ldmatrix, 2-stage) -----
// Tile: BM=128, BN=128, BK=32. 8 warps (2x4). Warp tile 64x32 = one head.
#define SA 20          // smem row stride in uint32 (40 fp16 = 80B, LDSM conflict-free)
#define BUFW (128 * SA)

__global__ __launch_bounds__(256, 2)
void gemm_kernel(const float* __restrict__ aL, const float* __restrict__ aR) {
    __shared__ uint32_t As[2 * BUFW];
    __shared__ uint32_t Bs[2 * BUFW];

    const int t    = threadIdx.x;
    const int m0   = blockIdx.x * 128;
    const int n0   = blockIdx.y * 128;
    const int wid  = t >> 5, lane = t & 31;
    const int wm   = wid >> 2, wn = wid & 3;    // 2 x 4 warp grid
    const int g    = lane >> 2, tt = lane & 3;

    const int r  = t >> 1;             // tile row 0..127
    const int kq = (t & 1) * 16;       // k-half in fp16 elements

    float c[4][4][4];
    #pragma unroll
    for (int i = 0; i < 4; i++)
        #pragma unroll
        for (int j = 0; j < 4; j++)
            #pragma unroll
            for (int k = 0; k < 4; k++) c[i][j][k] = 0.0f;

    const int mid = lane >> 3;            // ldmatrix matrix id 0..3
    const uint32_t As_u = (uint32_t)__cvta_generic_to_shared(As);
    const uint32_t Bs_u = (uint32_t)__cvta_generic_to_shared(Bs);
    int a_off[4];
    #pragma unroll
    for (int fm = 0; fm < 4; fm++)
        a_off[fm] = (wm * 64 + fm * 16 + (mid & 1) * 8 + (lane & 7)) * SA + (mid >> 1) * 4;
    int b_off[2];
    #pragma unroll
    for (int p = 0; p < 2; p++)
        b_off[p] = (wn * 32 + p * 16 + (mid >> 1) * 8 + (lane & 7)) * SA + (mid & 1) * 4;

    const int am = min(m0 + r, N_NODES - 1);   // clamp (dup rows, masked at store)
    uint4 va0, va1, vb0, vb1;
    auto loadTile = [&](int k0) {
        const uint4* pa = (const uint4*)&g_x16[(size_t)am * IN_CH + k0 + kq];
        va0 = pa[0]; va1 = pa[1];
        const uint4* pb = (const uint4*)&g_w16[(n0 + r) * IN_CH + k0 + kq];
        vb0 = pb[0]; vb1 = pb[1];
    };
    const int s_sts = r * SA + (kq >> 1);
    auto stsTile = [&](int buf) {
        int s = buf * BUFW + s_sts;
        *(uint4*)&As[s] = va0; *(uint4*)&As[s + 4] = va1;
        *(uint4*)&Bs[s] = vb0; *(uint4*)&Bs[s + 4] = vb1;
    };

    loadTile(0);
    stsTile(0);
    __syncthreads();

    #pragma unroll
    for (int it = 0; it < IN_CH / 32; it++) {
        const int buf = it & 1;
        const bool more = (it + 1) < IN_CH / 32;
        if (more) loadTile((it + 1) * 32);     // LDG overlaps this iter's MMA

        const uint32_t a_base = As_u + 4u * (uint32_t)(buf * BUFW);
        const uint32_t b_base = Bs_u + 4u * (uint32_t)(buf * BUFW);
        #pragma unroll
        for (int ks = 0; ks < 2; ks++) {
            const int kw = ks * 8;
            uint32_t bf[4][2];
            {
                uint32_t rr[4];
                ldsm_x4(rr, b_base + 4u * (b_off[0] + kw));
                bf[0][0] = rr[0]; bf[0][1] = rr[1]; bf[1][0] = rr[2]; bf[1][1] = rr[3];
                ldsm_x4(rr, b_base + 4u * (b_off[1] + kw));
                bf[2][0] = rr[0]; bf[2][1] = rr[1]; bf[3][0] = rr[2]; bf[3][1] = rr[3];
            }
            #pragma unroll
            for (int fm = 0; fm < 4; fm++) {
                uint32_t af[4];
                ldsm_x4(af, a_base + 4u * (a_off[fm] + kw));
                #pragma unroll
                for (int fn = 0; fn < 4; fn++)
                    mma_f16(c[fm][fn], af, bf[fn]);
            }
        }
        if (more) stsTile(buf ^ 1);            // write next buffer, then publish
        __syncthreads();
    }

    // ---- epilogue: store fp16 Wh + fused eL/eR ----
    const int h = blockIdx.y * 4 + wn;   // global head for this warp
    float aLv[8], aRv[8];
    #pragma unroll
    for (int fn = 0; fn < 4; fn++) {
        int c0 = fn * 8 + 2 * tt;
        aLv[2 * fn]     = aL[h * 32 + c0];
        aLv[2 * fn + 1] = aL[h * 32 + c0 + 1];
        aRv[2 * fn]     = aR[h * 32 + c0];
        aRv[2 * fn + 1] = aR[h * 32 + c0 + 1];
    }

    #pragma unroll
    for (int fm = 0; fm < 4; fm++) {
        int mrow = m0 + wm * 64 + fm * 16 + g;
        #pragma unroll
        for (int fn = 0; fn < 4; fn++) {
            int colp = (n0 + wn * 32 + fn * 8 + 2 * tt) >> 1;  // half2 index
            if (mrow < N_NODES)
                g_Whh[(size_t)mrow * (HC / 2) + colp] =
                    __floats2half2_rn(c[fm][fn][0], c[fm][fn][1]);
            if (mrow + 8 < N_NODES)
                g_Whh[(size_t)(mrow + 8) * (HC / 2) + colp] =
                    __floats2half2_rn(c[fm][fn][2], c[fm][fn][3]);
        }
        #pragma unroll
        for (int half = 0; half < 2; half++) {
            float pl = 0.f, pr = 0.f;
            #pragma unroll
            for (int fn = 0; fn < 4; fn++) {
                pl += c[fm][fn][2 * half] * aLv[2 * fn] + c[fm][fn][2 * half + 1] * aLv[2 * fn + 1];
                pr += c[fm][fn][2 * half] * aRv[2 * fn] + c[fm][fn][2 * half + 1] * aRv[2 * fn + 1];
            }
            pl += __shfl_xor_sync(0xffffffffu, pl, 1);
            pl += __shfl_xor_sync(0xffffffffu, pl, 2);
            pr += __shfl_xor_sync(0xffffffffu, pr, 1);
            pr += __shfl_xor_sync(0xffffffffu, pr, 2);
            int m = mrow + half * 8;
            if (tt == 0 && m < N_NODES) {
                g_eL[m * HEADS + h] = pl;
                g_eR[m * HEADS + h] = pr;
            }
        }
    }
}

// ---------------- degree count: 4 edges / thread ----------------
__global__ void deg_kernel(const void* __restrict__ ei) {
    int e4 = blockIdx.x * blockDim.x + threadIdx.x;
    if (e4 * 4 >= N_EDGES) return;
    int d[4];
    if (g_is64) {
        const longlong2* p = (const longlong2*)((const long long*)ei + N_EDGES) + e4 * 2;
        longlong2 v0 = p[0], v1 = p[1];
        d[0] = (int)v0.x; d[1] = (int)v0.y; d[2] = (int)v1.x; d[3] = (int)v1.y;
    } else {
        int4 v = ((const int4*)((const int*)ei + N_EDGES))[e4];
        d[0] = v.x; d[1] = v.y; d[2] = v.z; d[3] = v.w;
    }
    #pragma unroll
    for (int i = 0; i < 4; i++) atomicAdd(&g_deg[d[i]], 1);
}

// ---------------- scan phase 1: per-block sums ----------
__global__ __launch_bounds__(SCAN_CHUNK)
void scan1_kernel() {
    __shared__ int wsum[SCAN_CHUNK / 32];
    int t = threadIdx.x, lane = t & 31, w = t >> 5;
    int idx = blockIdx.x * SCAN_CHUNK + t;
    int v = (idx < N_NODES) ? g_deg[idx] : 0;
    #pragma unroll
    for (int off = 16; off > 0; off >>= 1) v += __shfl_down_sync(0xffffffffu, v, off);
    if (lane == 0) wsum[w] = v;
    __syncthreads();
    if (t < SCAN_CHUNK / 32) {
        int s = wsum[t];
        #pragma unroll
        for (int off = 8; off > 0; off >>= 1) s += __shfl_down_sync(0xffffu, s, off);
        if (t == 0) g_blocksum[blockIdx.x] = s;
    }
}

// ---------------- scan phase 3: block-local scan + inline block offset ----
__global__ __launch_bounds__(SCAN_CHUNK)
void scan3_kernel() {
    __shared__ int wsum[SCAN_CHUNK / 32];
    __shared__ int s_boff;
    int t = threadIdx.x, lane = t & 31, w = t >> 5;

    if (w == 0) {
        int s = 0;
        for (int j = lane; j < blockIdx.x; j += 32) s += g_blocksum[j];
        #pragma unroll
        for (int off = 16; off > 0; off >>= 1) s += __shfl_down_sync(0xffffffffu, s, off);
        if (lane == 0) s_boff = s;
    }

    int idx = blockIdx.x * SCAN_CHUNK + t;
    int v = (idx < N_NODES) ? g_deg[idx] : 0;
    int incl = v;
    #pragma unroll
    for (int off = 1; off < 32; off <<= 1) {
        int nb = __shfl_up_sync(0xffffffffu, incl, off);
        if (lane >= off) incl += nb;
    }
    if (lane == 31) wsum[w] = incl;
    __syncthreads();
    if (t < SCAN_CHUNK / 32) {
        int s = wsum[t];
        #pragma unroll
        for (int off = 1; off < SCAN_CHUNK / 32; off <<= 1) {
            int nb = __shfl_up_sync(0xffffu, s, off);
            if ((t & 15) >= off) s += nb;
        }
        wsum[t] = s;
    }
    __syncthreads();
    int incl_tot = incl + (w ? wsum[w - 1] : 0) + s_boff;
    if (idx < N_NODES) {
        g_cursor[idx]   = incl_tot - v;
        g_ptr[idx + 1]  = incl_tot;
    }
    if (idx == 0) g_ptr[0] = 0;
}

// ---------------- CSR fill: 4 edges / thread ----------------
__global__ void scatter_kernel(const void* __restrict__ ei) {
    int e4 = blockIdx.x * blockDim.x + threadIdx.x;
    if (e4 * 4 >= N_EDGES) return;
    int s[4], d[4];
    if (g_is64) {
        const longlong2* ps = (const longlong2*)ei + e4 * 2;
        const longlong2* pd = (const longlong2*)((const long long*)ei + N_EDGES) + e4 * 2;
        longlong2 s0 = ps[0], s1 = ps[1], d0 = pd[0], d1 = pd[1];
        s[0] = (int)s0.x; s[1] = (int)s0.y; s[2] = (int)s1.x; s[3] = (int)s1.y;
        d[0] = (int)d0.x; d[1] = (int)d0.y; d[2] = (int)d1.x; d[3] = (int)d1.y;
    } else {
        int4 vs = ((const int4*)ei)[e4];
        int4 vd = ((const int4*)((const int*)ei + N_EDGES))[e4];
        s[0] = vs.x; s[1] = vs.y; s[2] = vs.z; s[3] = vs.w;
        d[0] = vd.x; d[1] = vd.y; d[2] = vd.z; d[3] = vd.w;
    }
    #pragma unroll
    for (int i = 0; i < 4; i++) {
        int pos = atomicAdd(&g_cursor[d[i]], 1);
        g_csr_src[pos] = s[i];
    }
}

// ---------------- aggregation: warp-per-node, 8-wide batched FMA loop ----
__device__ __forceinline__ void fma_row(float* acc, float w, uint4 v) {
    float2 f0 = __half22float2(*reinterpret_cast<const __half2*>(&v.x));
    float2 f1 = __half22float2(*reinterpret_cast<const __half2*>(&v.y));
    float2 f2 = __half22float2(*reinterpret_cast<const __half2*>(&v.z));
    float2 f3 = __half22float2(*reinterpret_cast<const __half2*>(&v.w));
    acc[0] = fmaf(w, f0.x, acc[0]); acc[1] = fmaf(w, f0.y, acc[1]);
    acc[2] = fmaf(w, f1.x, acc[2]); acc[3] = fmaf(w, f1.y, acc[3]);
    acc[4] = fmaf(w, f2.x, acc[4]); acc[5] = fmaf(w, f2.y, acc[5]);
    acc[6] = fmaf(w, f3.x, acc[6]); acc[7] = fmaf(w, f3.y, acc[7]);
}

__global__ __launch_bounds__(256)
void agg_kernel(float* __restrict__ out) {
    __shared__ float s_w[8][32][9];   // [warp][edge][head], stride 9: conflict-free

    const int lane = threadIdx.x & 31;
    const int wix  = threadIdx.x >> 5;            // warp in block
    const int n = blockIdx.x * 8 + wix;
    if (n >= N_NODES) return;

    const int hq = lane >> 2;                     // head for FMA phase (channels)

    float er[8];
    {
        float4 r0 = *(const float4*)&g_eR[n * HEADS];
        float4 r1 = *(const float4*)&g_eR[n * HEADS + 4];
        er[0] = r0.x; er[1] = r0.y; er[2] = r0.z; er[3] = r0.w;
        er[4] = r1.x; er[5] = r1.y; er[6] = r1.z; er[7] = r1.w;
    }

    float acc[8];
    float denom;
    {
        float4 l0 = *(const float4*)&g_eL[n * HEADS];
        float4 l1 = *(const float4*)&g_eL[n * HEADS + 4];
        float el[8] = {l0.x, l0.y, l0.z, l0.w, l1.x, l1.y, l1.z, l1.w};
        float s = el[hq] + er[hq];
        s = fmaxf(s, NEG_SLOPE * s);
        float wself = __expf(s);
        uint4 v = ((const uint4*)&g_Whh[(size_t)n * (HC / 2)])[lane];
        float2 f0 = __half22float2(*reinterpret_cast<const __half2*>(&v.x));
        float2 f1 = __half22float2(*reinterpret_cast<const __half2*>(&v.y));
        float2 f2 = __half22float2(*reinterpret_cast<const __half2*>(&v.z));
        float2 f3 = __half22float2(*reinterpret_cast<const __half2*>(&v.w));
        acc[0] = wself * f0.x; acc[1] = wself * f0.y;
        acc[2] = wself * f1.x; acc[3] = wself * f1.y;
        acc[4] = wself * f2.x; acc[5] = wself * f2.y;
        acc[6] = wself * f3.x; acc[7] = wself * f3.y;
        denom = wself;
    }

    const int beg = g_ptr[n];
    const int end = g_ptr[n + 1];

    for (int base = beg; base < end; base += 32) {
        int cnt = min(32, end - base);
        int src_l = 0;
        if (lane < cnt) {
            src_l = g_csr_src[base + lane];
            float4 l0 = *(const float4*)&g_eL[src_l * HEADS];
            float4 l1 = *(const float4*)&g_eL[src_l * HEADS + 4];
            float el[8] = {l0.x, l0.y, l0.z, l0.w, l1.x, l1.y, l1.z, l1.w};
            #pragma unroll
            for (int h = 0; h < 8; h++) {
                float s = el[h] + er[h];
                s = fmaxf(s, NEG_SLOPE * s);
                s_w[wix][lane][h] = __expf(s);
            }
        }
        __syncwarp();

        int k = 0;
        // 8-wide batches: 8 independent LDG.128 in flight
        for (; k + 8 <= cnt; k += 8) {
            int s0 = __shfl_sync(0xffffffffu, src_l, k);
            int s1 = __shfl_sync(0xffffffffu, src_l, k + 1);
            int s2 = __shfl_sync(0xffffffffu, src_l, k + 2);
            int s3 = __shfl_sync(0xffffffffu, src_l, k + 3);
            int s4 = __shfl_sync(0xffffffffu, src_l, k + 4);
            int s5 = __shfl_sync(0xffffffffu, src_l, k + 5);
            int s6 = __shfl_sync(0xffffffffu, src_l, k + 6);
            int s7 = __shfl_sync(0xffffffffu, src_l, k + 7);
            uint4 v0 = ((const uint4*)&g_Whh[(size_t)s0 * (HC / 2)])[lane];
            uint4 v1 = ((const uint4*)&g_Whh[(size_t)s1 * (HC / 2)])[lane];
            uint4 v2 = ((const uint4*)&g_Whh[(size_t)s2 * (HC / 2)])[lane];
            uint4 v3 = ((const uint4*)&g_Whh[(size_t)s3 * (HC / 2)])[lane];
            uint4 v4 = ((const uint4*)&g_Whh[(size_t)s4 * (HC / 2)])[lane];
            uint4 v5 = ((const uint4*)&g_Whh[(size_t)s5 * (HC / 2)])[lane];
            uint4 v6 = ((const uint4*)&g_Whh[(size_t)s6 * (HC / 2)])[lane];
            uint4 v7 = ((const uint4*)&g_Whh[(size_t)s7 * (HC / 2)])[lane];
            float w0 = s_w[wix][k][hq],     w1 = s_w[wix][k + 1][hq];
            float w2 = s_w[wix][k + 2][hq], w3 = s_w[wix][k + 3][hq];
            float w4 = s_w[wix][k + 4][hq], w5 = s_w[wix][k + 5][hq];
            float w6 = s_w[wix][k + 6][hq], w7 = s_w[wix][k + 7][hq];
            fma_row(acc, w0, v0); denom += w0;
            fma_row(acc, w1, v1); denom += w1;
            fma_row(acc, w2, v2); denom += w2;
            fma_row(acc, w3, v3); denom += w3;
            fma_row(acc, w4, v4); denom += w4;
            fma_row(acc, w5, v5); denom += w5;
            fma_row(acc, w6, v6); denom += w6;
            fma_row(acc, w7, v7); denom += w7;
        }
        // 4-wide tail
        for (; k + 4 <= cnt; k += 4) {
            int s0 = __shfl_sync(0xffffffffu, src_l, k);
            int s1 = __shfl_sync(0xffffffffu, src_l, k + 1);
            int s2 = __shfl_sync(0xffffffffu, src_l, k + 2);
            int s3 = __shfl_sync(0xffffffffu, src_l, k + 3);
            uint4 v0 = ((const uint4*)&g_Whh[(size_t)s0 * (HC / 2)])[lane];
            uint4 v1 = ((const uint4*)&g_Whh[(size_t)s1 * (HC / 2)])[lane];
            uint4 v2 = ((const uint4*)&g_Whh[(size_t)s2 * (HC / 2)])[lane];
            uint4 v3 = ((const uint4*)&g_Whh[(size_t)s3 * (HC / 2)])[lane];
            float w0 = s_w[wix][k][hq],     w1 = s_w[wix][k + 1][hq];
            float w2 = s_w[wix][k + 2][hq], w3 = s_w[wix][k + 3][hq];
            fma_row(acc, w0, v0); denom += w0;
            fma_row(acc, w1, v1); denom += w1;
            fma_row(acc, w2, v2); denom += w2;
            fma_row(acc, w3, v3); denom += w3;
        }
        // scalar tail
        for (; k < cnt; k++) {
            int src = __shfl_sync(0xffffffffu, src_l, k);
            float w = s_w[wix][k][hq];
            uint4 v = ((const uint4*)&g_Whh[(size_t)src * (HC / 2)])[lane];
            fma_row(acc, w, v);
            denom += w;
        }
        __syncwarp();
    }

    float inv = 1.0f / (denom + 1e-16f);
    float* op = out + (size_t)n * HC + lane * 8;
    *(float4*)op       = make_float4(acc[0] * inv, acc[1] * inv, acc[2] * inv, acc[3] * inv);
    *(float4*)(op + 4) = make_float4(acc[4] * inv, acc[5] * inv, acc[6] * inv, acc[7] * inv);
}

// ---------------- launch: forked-capture dual stream ----------------
extern "C" void kernel_launch(void* const* d_in, const int* in_sizes, int n_in,
                              void* d_out, int out_size) {
    const float* x  = (const float*)d_in[0];
    const void*  ei = (const void*)d_in[1];
    const float* W  = (const float*)d_in[2];
    const float* aL = (const float*)d_in[3];
    const float* aR = (const float*)d_in[4];
    float* out = (float*)d_out;

    cudaStream_t s2;
    cudaStreamCreateWithFlags(&s2, cudaStreamNonBlocking);
    cudaEvent_t eFork, eJoin;
    cudaEventCreateWithFlags(&eFork, cudaEventDisableTiming);
    cudaEventCreateWithFlags(&eJoin, cudaEventDisableTiming);

    // fork: edge-prep chain on s2, gemm chain on default stream
    cudaEventRecord(eFork, 0);
    cudaStreamWaitEvent(s2, eFork, 0);

    cvt_kernel<<<(CVT_THREADS + 255) / 256, 256>>>(x, W);                           // 0 (s0)
    init_edge_kernel<<<(N_NODES + 255) / 256, 256, 0, s2>>>((const int*)ei);        // 1 (s2)
    deg_kernel<<<(N_EDGES / 4 + 255) / 256, 256, 0, s2>>>(ei);                      // 2 (s2)

    dim3 ggrid((N_NODES + 127) / 128, HC / 128);
    gemm_kernel<<<ggrid, 256>>>(aL, aR);                                            // 3 (s0) <- profiled

    scan1_kernel<<<SCAN_BLOCKS, SCAN_CHUNK, 0, s2>>>();                             // 4 (s2)
    scan3_kernel<<<SCAN_BLOCKS, SCAN_CHUNK, 0, s2>>>();                             // 5 (s2)
    scatter_kernel<<<(N_EDGES / 4 + 255) / 256, 256, 0, s2>>>(ei);                  // 6 (s2)
    cudaEventRecord(eJoin, s2);

    // join: agg needs CSR (s2) + Wh/eL/eR (s0)
    cudaStreamWaitEvent(0, eJoin, 0);
    agg_kernel<<<(N_NODES + 7) / 8, 256>>>(out);                                    // 7 (s0)

    cudaEventDestroy(eFork);
    cudaEventDestroy(eJoin);
    cudaStreamDestroy(s2);
}

// round 16
// speedup vs baseline: 1.6758x; 1.0649x over previous
#include <cuda_runtime.h>
#include <cuda_bf16.h>
#include <cuda_fp16.h>
#include <cstdint>

// ---------------- problem constants ----------------
#define N_NODES   50000
#define N_EDGES   800000
#define IN_CH     256
#define HEADS     8
#define OUT_CH    32
#define HC        256          // HEADS*OUT_CH
#define NEG_SLOPE 0.2f

#define SCAN_CHUNK  512
#define SCAN_BLOCKS ((N_NODES + SCAN_CHUNK - 1) / SCAN_CHUNK)   // 98

// ---------------- device scratch ----------------
__device__ __half2 g_Whh[(size_t)N_NODES * (HC / 2)];    // 25.6 MB fp16 Wh
__device__ ushort  g_w16[HC * IN_CH];                    // 128 KB fp16 W
__device__ float g_eL[N_NODES * HEADS];
__device__ float g_eR[N_NODES * HEADS];
__device__ int   g_deg[N_NODES];
__device__ int   g_ptr[N_NODES + 1];
__device__ int   g_cursor[N_NODES];
__device__ int   g_csr_src[N_EDGES];
__device__ int   g_blocksum[SCAN_BLOCKS];
__device__ int   g_is64;

#define W_CVT_THREADS (HC * IN_CH / 8)        // 8,192

__device__ __forceinline__ uint32_t f2h2(float x, float y) {
    __half2 h = __floats2half2_rn(x, y);
    return *reinterpret_cast<uint32_t*>(&h);
}

// ---------------- W fp16 conversion (tiny, stream 0) ----------------
__global__ void cvt_w_kernel(const float* __restrict__ W) {
    int i = blockIdx.x * blockDim.x + threadIdx.x;
    if (i < W_CVT_THREADS) {
        size_t off = (size_t)i * 8;
        float4 a = *(const float4*)(W + off);
        float4 b = *(const float4*)(W + off + 4);
        uint4 h;
        h.x = f2h2(a.x, a.y); h.y = f2h2(a.z, a.w);
        h.z = f2h2(b.x, b.y); h.w = f2h2(b.z, b.w);
        *(uint4*)(g_w16 + off) = h;
    }
}

// ---------------- edge-chain init: detect dtype + zero deg (stream 2) ----
__global__ void init_edge_kernel(const int* ei_words) {
    int i = blockIdx.x * blockDim.x + threadIdx.x;
    if (i == 0) {
        int all0 = 1;
        for (int k = 0; k < 64; k++) {
            if (ei_words[2 * k + 1] != 0) { all0 = 0; break; }
        }
        g_is64 = all0;
    }
    if (i < N_NODES) g_deg[i] = 0;
}

// ---------------- tensor-core primitives ----------------
__device__ __forceinline__ void mma_f16(float* c, const uint32_t* a, const uint32_t* b) {
    asm volatile(
        "mma.sync.aligned.m16n8k16.row.col.f32.f16.f16.f32 "
        "{%0,%1,%2,%3}, {%4,%5,%6,%7}, {%8,%9}, {%0,%1,%2,%3};\n"
        : "+f"(c[0]), "+f"(c[1]), "+f"(c[2]), "+f"(c[3])
        : "r"(a[0]), "r"(a[1]), "r"(a[2]), "r"(a[3]), "r"(b[0]), "r"(b[1]));
}

__device__ __forceinline__ void ldsm_x4(uint32_t* r, uint32_t addr) {
    asm volatile("ldmatrix.sync.aligned.m8n8.x4.shared.b16 {%0,%1,%2,%3}, [%4];"
        : "=r"(r[0]), "=r"(r[1]), "=r"(r[2]), "=r"(r[3]) : "r"(addr));
}

// ---------------- GEMM: Wh = x @ W^T  (BM=128, BN=256, one pass over x) --
// 512 threads, 16 warps (2x8). Warp tile 64x32 = one head wide.
// A converted fp32->fp16 inline (x read ONCE); B pre-converted fp16.
#define SA 20   // smem row stride in uint32 (40 fp16 = 80B, LDSM conflict-free)

__global__ __launch_bounds__(512, 1)
void gemm_kernel(const float* __restrict__ x,
                 const float* __restrict__ aL, const float* __restrict__ aR) {
    __shared__ uint32_t As[128 * SA];
    __shared__ uint32_t Bs[256 * SA];

    const int t    = threadIdx.x;
    const int m0   = blockIdx.x * 128;
    const int wid  = t >> 5, lane = t & 31;
    const int wm   = wid >> 3, wn = wid & 7;    // 2 x 8 warp grid
    const int g    = lane >> 2, tt = lane & 3;

    // A loader: 128 rows x 32 k fp32; 8 fp32 per thread
    const int ra  = t >> 2;
    const int kqa = (t & 3) * 8;
    // B loader: 256 rows x 32 k fp16; 16 fp16 per thread
    const int rb  = t >> 1;
    const int kqb = (t & 1) * 16;

    float c[4][4][4];
    #pragma unroll
    for (int i = 0; i < 4; i++)
        #pragma unroll
        for (int j = 0; j < 4; j++)
            #pragma unroll
            for (int k = 0; k < 4; k++) c[i][j][k] = 0.0f;

    const int mid = lane >> 3;            // ldmatrix matrix id 0..3
    const uint32_t As_u = (uint32_t)__cvta_generic_to_shared(As);
    const uint32_t Bs_u = (uint32_t)__cvta_generic_to_shared(Bs);
    int a_off[4];
    #pragma unroll
    for (int fm = 0; fm < 4; fm++)
        a_off[fm] = (wm * 64 + fm * 16 + (mid & 1) * 8 + (lane & 7)) * SA + (mid >> 1) * 4;
    int b_off[2];
    #pragma unroll
    for (int p = 0; p < 2; p++)
        b_off[p] = (wn * 32 + p * 16 + (mid >> 1) * 8 + (lane & 7)) * SA + (mid & 1) * 4;

    const int am = min(m0 + ra, N_NODES - 1);   // clamp (dup rows, masked at store)
    uint4 va, vb0, vb1;
    auto loadTile = [&](int k0) {
        // A: 8 fp32 -> 4 half2 words (convert immediately, short fp32 live range)
        const float4* pa = (const float4*)(x + (size_t)am * IN_CH + k0 + kqa);
        float4 a0 = pa[0], a1 = pa[1];
        va.x = f2h2(a0.x, a0.y); va.y = f2h2(a0.z, a0.w);
        va.z = f2h2(a1.x, a1.y); va.w = f2h2(a1.z, a1.w);
        // B: already fp16, 16 halves = 2 uint4
        const uint4* pb = (const uint4*)&g_w16[rb * IN_CH + k0 + kqb];
        vb0 = pb[0]; vb1 = pb[1];
    };
    const int sa_sts = ra * SA + (kqa >> 1);
    const int sb_sts = rb * SA + (kqb >> 1);
    auto stsTile = [&]() {
        *(uint4*)&As[sa_sts]     = va;
        *(uint4*)&Bs[sb_sts]     = vb0;
        *(uint4*)&Bs[sb_sts + 4] = vb1;
    };

    loadTile(0);

    #pragma unroll
    for (int it = 0; it < IN_CH / 32; it++) {
        stsTile();
        __syncthreads();
        if (it + 1 < IN_CH / 32) loadTile((it + 1) * 32);  // prefetch overlaps MMA

        #pragma unroll
        for (int ks = 0; ks < 2; ks++) {
            const int kw = ks * 8;
            uint32_t bf[4][2];
            {
                uint32_t rr[4];
                ldsm_x4(rr, Bs_u + 4u * (b_off[0] + kw));
                bf[0][0] = rr[0]; bf[0][1] = rr[1]; bf[1][0] = rr[2]; bf[1][1] = rr[3];
                ldsm_x4(rr, Bs_u + 4u * (b_off[1] + kw));
                bf[2][0] = rr[0]; bf[2][1] = rr[1]; bf[3][0] = rr[2]; bf[3][1] = rr[3];
            }
            #pragma unroll
            for (int fm = 0; fm < 4; fm++) {
                uint32_t af[4];
                ldsm_x4(af, As_u + 4u * (a_off[fm] + kw));
                #pragma unroll
                for (int fn = 0; fn < 4; fn++)
                    mma_f16(c[fm][fn], af, bf[fn]);
            }
        }
        __syncthreads();
    }

    // ---- epilogue: store fp16 Wh + fused eL/eR ----
    const int h = wn;   // global head for this warp (grid.y gone)
    float aLv[8], aRv[8];
    #pragma unroll
    for (int fn = 0; fn < 4; fn++) {
        int c0 = fn * 8 + 2 * tt;
        aLv[2 * fn]     = aL[h * 32 + c0];
        aLv[2 * fn + 1] = aL[h * 32 + c0 + 1];
        aRv[2 * fn]     = aR[h * 32 + c0];
        aRv[2 * fn + 1] = aR[h * 32 + c0 + 1];
    }

    #pragma unroll
    for (int fm = 0; fm < 4; fm++) {
        int mrow = m0 + wm * 64 + fm * 16 + g;
        #pragma unroll
        for (int fn = 0; fn < 4; fn++) {
            int colp = (wn * 32 + fn * 8 + 2 * tt) >> 1;  // half2 index
            if (mrow < N_NODES)
                g_Whh[(size_t)mrow * (HC / 2) + colp] =
                    __floats2half2_rn(c[fm][fn][0], c[fm][fn][1]);
            if (mrow + 8 < N_NODES)
                g_Whh[(size_t)(mrow + 8) * (HC / 2) + colp] =
                    __floats2half2_rn(c[fm][fn][2], c[fm][fn][3]);
        }
        #pragma unroll
        for (int half = 0; half < 2; half++) {
            float pl = 0.f, pr = 0.f;
            #pragma unroll
            for (int fn = 0; fn < 4; fn++) {
                pl += c[fm][fn][2 * half] * aLv[2 * fn] + c[fm][fn][2 * half + 1] * aLv[2 * fn + 1];
                pr += c[fm][fn][2 * half] * aRv[2 * fn] + c[fm][fn][2 * half + 1] * aRv[2 * fn + 1];
            }
            pl += __shfl_xor_sync(0xffffffffu, pl, 1);
            pl += __shfl_xor_sync(0xffffffffu, pl, 2);
            pr += __shfl_xor_sync(0xffffffffu, pr, 1);
            pr += __shfl_xor_sync(0xffffffffu, pr, 2);
            int m = mrow + half * 8;
            if (tt == 0 && m < N_NODES) {
                g_eL[m * HEADS + h] = pl;
                g_eR[m * HEADS + h] = pr;
            }
        }
    }
}

// ---------------- degree count: 4 edges / thread ----------------
__global__ void deg_kernel(const void* __restrict__ ei) {
    int e4 = blockIdx.x * blockDim.x + threadIdx.x;
    if (e4 * 4 >= N_EDGES) return;
    int d[4];
    if (g_is64) {
        const longlong2* p = (const longlong2*)((const long long*)ei + N_EDGES) + e4 * 2;
        longlong2 v0 = p[0], v1 = p[1];
        d[0] = (int)v0.x; d[1] = (int)v0.y; d[2] = (int)v1.x; d[3] = (int)v1.y;
    } else {
        int4 v = ((const int4*)((const int*)ei + N_EDGES))[e4];
        d[0] = v.x; d[1] = v.y; d[2] = v.z; d[3] = v.w;
    }
    #pragma unroll
    for (int i = 0; i < 4; i++) atomicAdd(&g_deg[d[i]], 1);
}

// ---------------- scan phase 1: per-block sums ----------
__global__ __launch_bounds__(SCAN_CHUNK)
void scan1_kernel() {
    __shared__ int wsum[SCAN_CHUNK / 32];
    int t = threadIdx.x, lane = t & 31, w = t >> 5;
    int idx = blockIdx.x * SCAN_CHUNK + t;
    int v = (idx < N_NODES) ? g_deg[idx] : 0;
    #pragma unroll
    for (int off = 16; off > 0; off >>= 1) v += __shfl_down_sync(0xffffffffu, v, off);
    if (lane == 0) wsum[w] = v;
    __syncthreads();
    if (t < SCAN_CHUNK / 32) {
        int s = wsum[t];
        #pragma unroll
        for (int off = 8; off > 0; off >>= 1) s += __shfl_down_sync(0xffffu, s, off);
        if (t == 0) g_blocksum[blockIdx.x] = s;
    }
}

// ---------------- scan phase 3: block-local scan + inline block offset ----
__global__ __launch_bounds__(SCAN_CHUNK)
void scan3_kernel() {
    __shared__ int wsum[SCAN_CHUNK / 32];
    __shared__ int s_boff;
    int t = threadIdx.x, lane = t & 31, w = t >> 5;

    if (w == 0) {
        int s = 0;
        for (int j = lane; j < blockIdx.x; j += 32) s += g_blocksum[j];
        #pragma unroll
        for (int off = 16; off > 0; off >>= 1) s += __shfl_down_sync(0xffffffffu, s, off);
        if (lane == 0) s_boff = s;
    }

    int idx = blockIdx.x * SCAN_CHUNK + t;
    int v = (idx < N_NODES) ? g_deg[idx] : 0;
    int incl = v;
    #pragma unroll
    for (int off = 1; off < 32; off <<= 1) {
        int nb = __shfl_up_sync(0xffffffffu, incl, off);
        if (lane >= off) incl += nb;
    }
    if (lane == 31) wsum[w] = incl;
    __syncthreads();
    if (t < SCAN_CHUNK / 32) {
        int s = wsum[t];
        #pragma unroll
        for (int off = 1; off < SCAN_CHUNK / 32; off <<= 1) {
            int nb = __shfl_up_sync(0xffffu, s, off);
            if ((t & 15) >= off) s += nb;
        }
        wsum[t] = s;
    }
    __syncthreads();
    int incl_tot = incl + (w ? wsum[w - 1] : 0) + s_boff;
    if (idx < N_NODES) {
        g_cursor[idx]   = incl_tot - v;
        g_ptr[idx + 1]  = incl_tot;
    }
    if (idx == 0) g_ptr[0] = 0;
}

// ---------------- CSR fill: 4 edges / thread ----------------
__global__ void scatter_kernel(const void* __restrict__ ei) {
    int e4 = blockIdx.x * blockDim.x + threadIdx.x;
    if (e4 * 4 >= N_EDGES) return;
    int s[4], d[4];
    if (g_is64) {
        const longlong2* ps = (const longlong2*)ei + e4 * 2;
        const longlong2* pd = (const longlong2*)((const long long*)ei + N_EDGES) + e4 * 2;
        longlong2 s0 = ps[0], s1 = ps[1], d0 = pd[0], d1 = pd[1];
        s[0] = (int)s0.x; s[1] = (int)s0.y; s[2] = (int)s1.x; s[3] = (int)s1.y;
        d[0] = (int)d0.x; d[1] = (int)d0.y; d[2] = (int)d1.x; d[3] = (int)d1.y;
    } else {
        int4 vs = ((const int4*)ei)[e4];
        int4 vd = ((const int4*)((const int*)ei + N_EDGES))[e4];
        s[0] = vs.x; s[1] = vs.y; s[2] = vs.z; s[3] = vs.w;
        d[0] = vd.x; d[1] = vd.y; d[2] = vd.z; d[3] = vd.w;
    }
    #pragma unroll
    for (int i = 0; i < 4; i++) {
        int pos = atomicAdd(&g_cursor[d[i]], 1);
        g_csr_src[pos] = s[i];
    }
}

// ---------------- aggregation: warp-per-node, 8-wide batched FMA loop ----
__device__ __forceinline__ void fma_row(float* acc, float w, uint4 v) {
    float2 f0 = __half22float2(*reinterpret_cast<const __half2*>(&v.x));
    float2 f1 = __half22float2(*reinterpret_cast<const __half2*>(&v.y));
    float2 f2 = __half22float2(*reinterpret_cast<const __half2*>(&v.z));
    float2 f3 = __half22float2(*reinterpret_cast<const __half2*>(&v.w));
    acc[0] = fmaf(w, f0.x, acc[0]); acc[1] = fmaf(w, f0.y, acc[1]);
    acc[2] = fmaf(w, f1.x, acc[2]); acc[3] = fmaf(w, f1.y, acc[3]);
    acc[4] = fmaf(w, f2.x, acc[4]); acc[5] = fmaf(w, f2.y, acc[5]);
    acc[6] = fmaf(w, f3.x, acc[6]); acc[7] = fmaf(w, f3.y, acc[7]);
}

__global__ __launch_bounds__(256)
void agg_kernel(float* __restrict__ out) {
    __shared__ float s_w[8][32][9];   // [warp][edge][head], stride 9: conflict-free

    const int lane = threadIdx.x & 31;
    const int wix  = threadIdx.x >> 5;            // warp in block
    const int n = blockIdx.x * 8 + wix;
    if (n >= N_NODES) return;

    const int hq = lane >> 2;                     // head for FMA phase (channels)

    float er[8];
    {
        float4 r0 = *(const float4*)&g_eR[n * HEADS];
        float4 r1 = *(const float4*)&g_eR[n * HEADS + 4];
        er[0] = r0.x; er[1] = r0.y; er[2] = r0.z; er[3] = r0.w;
        er[4] = r1.x; er[5] = r1.y; er[6] = r1.z; er[7] = r1.w;
    }

    float acc[8];
    float denom;
    {
        float4 l0 = *(const float4*)&g_eL[n * HEADS];
        float4 l1 = *(const float4*)&g_eL[n * HEADS + 4];
        float el[8] = {l0.x, l0.y, l0.z, l0.w, l1.x, l1.y, l1.z, l1.w};
        float s = el[hq] + er[hq];
        s = fmaxf(s, NEG_SLOPE * s);
        float wself = __expf(s);
        uint4 v = ((const uint4*)&g_Whh[(size_t)n * (HC / 2)])[lane];
        float2 f0 = __half22float2(*reinterpret_cast<const __half2*>(&v.x));
        float2 f1 = __half22float2(*reinterpret_cast<const __half2*>(&v.y));
        float2 f2 = __half22float2(*reinterpret_cast<const __half2*>(&v.z));
        float2 f3 = __half22float2(*reinterpret_cast<const __half2*>(&v.w));
        acc[0] = wself * f0.x; acc[1] = wself * f0.y;
        acc[2] = wself * f1.x; acc[3] = wself * f1.y;
        acc[4] = wself * f2.x; acc[5] = wself * f2.y;
        acc[6] = wself * f3.x; acc[7] = wself * f3.y;
        denom = wself;
    }

    const int beg = g_ptr[n];
    const int end = g_ptr[n + 1];

    for (int base = beg; base < end; base += 32) {
        int cnt = min(32, end - base);
        int src_l = 0;
        if (lane < cnt) {
            src_l = g_csr_src[base + lane];
            float4 l0 = *(const float4*)&g_eL[src_l * HEADS];
            float4 l1 = *(const float4*)&g_eL[src_l * HEADS + 4];
            float el[8] = {l0.x, l0.y, l0.z, l0.w, l1.x, l1.y, l1.z, l1.w};
            #pragma unroll
            for (int h = 0; h < 8; h++) {
                float s = el[h] + er[h];
                s = fmaxf(s, NEG_SLOPE * s);
                s_w[wix][lane][h] = __expf(s);
            }
        }
        __syncwarp();

        int k = 0;
        for (; k + 8 <= cnt; k += 8) {
            int s0 = __shfl_sync(0xffffffffu, src_l, k);
            int s1 = __shfl_sync(0xffffffffu, src_l, k + 1);
            int s2 = __shfl_sync(0xffffffffu, src_l, k + 2);
            int s3 = __shfl_sync(0xffffffffu, src_l, k + 3);
            int s4 = __shfl_sync(0xffffffffu, src_l, k + 4);
            int s5 = __shfl_sync(0xffffffffu, src_l, k + 5);
            int s6 = __shfl_sync(0xffffffffu, src_l, k + 6);
            int s7 = __shfl_sync(0xffffffffu, src_l, k + 7);
            uint4 v0 = ((const uint4*)&g_Whh[(size_t)s0 * (HC / 2)])[lane];
            uint4 v1 = ((const uint4*)&g_Whh[(size_t)s1 * (HC / 2)])[lane];
            uint4 v2 = ((const uint4*)&g_Whh[(size_t)s2 * (HC / 2)])[lane];
            uint4 v3 = ((const uint4*)&g_Whh[(size_t)s3 * (HC / 2)])[lane];
            uint4 v4 = ((const uint4*)&g_Whh[(size_t)s4 * (HC / 2)])[lane];
            uint4 v5 = ((const uint4*)&g_Whh[(size_t)s5 * (HC / 2)])[lane];
            uint4 v6 = ((const uint4*)&g_Whh[(size_t)s6 * (HC / 2)])[lane];
            uint4 v7 = ((const uint4*)&g_Whh[(size_t)s7 * (HC / 2)])[lane];
            float w0 = s_w[wix][k][hq],     w1 = s_w[wix][k + 1][hq];
            float w2 = s_w[wix][k + 2][hq], w3 = s_w[wix][k + 3][hq];
            float w4 = s_w[wix][k + 4][hq], w5 = s_w[wix][k + 5][hq];
            float w6 = s_w[wix][k + 6][hq], w7 = s_w[wix][k + 7][hq];
            fma_row(acc, w0, v0); denom += w0;
            fma_row(acc, w1, v1); denom += w1;
            fma_row(acc, w2, v2); denom += w2;
            fma_row(acc, w3, v3); denom += w3;
            fma_row(acc, w4, v4); denom += w4;
            fma_row(acc, w5, v5); denom += w5;
            fma_row(acc, w6, v6); denom += w6;
            fma_row(acc, w7, v7); denom += w7;
        }
        for (; k + 4 <= cnt; k += 4) {
            int s0 = __shfl_sync(0xffffffffu, src_l, k);
            int s1 = __shfl_sync(0xffffffffu, src_l, k + 1);
            int s2 = __shfl_sync(0xffffffffu, src_l, k + 2);
            int s3 = __shfl_sync(0xffffffffu, src_l, k + 3);
            uint4 v0 = ((const uint4*)&g_Whh[(size_t)s0 * (HC / 2)])[lane];
            uint4 v1 = ((const uint4*)&g_Whh[(size_t)s1 * (HC / 2)])[lane];
            uint4 v2 = ((const uint4*)&g_Whh[(size_t)s2 * (HC / 2)])[lane];
            uint4 v3 = ((const uint4*)&g_Whh[(size_t)s3 * (HC / 2)])[lane];
            float w0 = s_w[wix][k][hq],     w1 = s_w[wix][k + 1][hq];
            float w2 = s_w[wix][k + 2][hq], w3 = s_w[wix][k + 3][hq];
            fma_row(acc, w0, v0); denom += w0;
            fma_row(acc, w1, v1); denom += w1;
            fma_row(acc, w2, v2); denom += w2;
            fma_row(acc, w3, v3); denom += w3;
        }
        for (; k < cnt; k++) {
            int src = __shfl_sync(0xffffffffu, src_l, k);
            float w = s_w[wix][k][hq];
            uint4 v = ((const uint4*)&g_Whh[(size_t)src * (HC / 2)])[lane];
            fma_row(acc, w, v);
            denom += w;
        }
        __syncwarp();
    }

    float inv = 1.0f / (denom + 1e-16f);
    float* op = out + (size_t)n * HC + lane * 8;
    *(float4*)op       = make_float4(acc[0] * inv, acc[1] * inv, acc[2] * inv, acc[3] * inv);
    *(float4*)(op + 4) = make_float4(acc[4] * inv, acc[5] * inv, acc[6] * inv, acc[7] * inv);
}

// ---------------- launch: forked-capture dual stream ----------------
extern "C" void kernel_launch(void* const* d_in, const int* in_sizes, int n_in,
                              void* d_out, int out_size) {
    const float* x  = (const float*)d_in[0];
    const void*  ei = (const void*)d_in[1];
    const float* W  = (const float*)d_in[2];
    const float* aL = (const float*)d_in[3];
    const float* aR = (const float*)d_in[4];
    float* out = (float*)d_out;

    cudaStream_t s2;
    cudaStreamCreateWithFlags(&s2, cudaStreamNonBlocking);
    cudaEvent_t eFork, eJoin;
    cudaEventCreateWithFlags(&eFork, cudaEventDisableTiming);
    cudaEventCreateWithFlags(&eJoin, cudaEventDisableTiming);

    // fork: edge-prep chain on s2, gemm chain on default stream
    cudaEventRecord(eFork, 0);
    cudaStreamWaitEvent(s2, eFork, 0);

    cvt_w_kernel<<<(W_CVT_THREADS + 255) / 256, 256>>>(W);                          // 0 (s0)
    init_edge_kernel<<<(N_NODES + 255) / 256, 256, 0, s2>>>((const int*)ei);        // 1 (s2)
    deg_kernel<<<(N_EDGES / 4 + 255) / 256, 256, 0, s2>>>(ei);                      // 2 (s2)

    gemm_kernel<<<(N_NODES + 127) / 128, 512>>>(x, aL, aR);                         // 3 (s0) <- profiled

    scan1_kernel<<<SCAN_BLOCKS, SCAN_CHUNK, 0, s2>>>();                             // 4 (s2)
    scan3_kernel<<<SCAN_BLOCKS, SCAN_CHUNK, 0, s2>>>();                             // 5 (s2)
    scatter_kernel<<<(N_EDGES / 4 + 255) / 256, 256, 0, s2>>>(ei);                  // 6 (s2)
    cudaEventRecord(eJoin, s2);

    // join: agg needs CSR (s2) + Wh/eL/eR (s0)
    cudaStreamWaitEvent(0, eJoin, 0);
    agg_kernel<<<(N_NODES + 7) / 8, 256>>>(out);                                    // 7 (s0)

    cudaEventDestroy(eFork);
    cudaEventDestroy(eJoin);
    cudaStreamDestroy(s2);
}

// round 17
// speedup vs baseline: 1.6767x; 1.0005x over previous
#include <cuda_runtime.h>
#include <cuda_bf16.h>
#include <cuda_fp16.h>
#include <cstdint>

// ---------------- problem constants ----------------
#define N_NODES   50000
#define N_EDGES   800000
#define IN_CH     256
#define HEADS     8
#define OUT_CH    32
#define HC        256          // HEADS*OUT_CH
#define NEG_SLOPE 0.2f

#define SCAN_CHUNK  512
#define SCAN_BLOCKS ((N_NODES + SCAN_CHUNK - 1) / SCAN_CHUNK)   // 98

// ---------------- device scratch ----------------
__device__ __half2 g_Whh[(size_t)N_NODES * (HC / 2)];    // 25.6 MB fp16 Wh
__device__ ushort  g_w16[HC * IN_CH];                    // 128 KB fp16 W
__device__ float g_eL[N_NODES * HEADS];
__device__ float g_eR[N_NODES * HEADS];
__device__ int   g_deg[N_NODES];
__device__ int   g_ptr[N_NODES + 1];
__device__ int   g_cursor[N_NODES];
__device__ int   g_csr_src[N_EDGES];
__device__ int   g_blocksum[SCAN_BLOCKS];
__device__ int   g_is64;

#define W_CVT_THREADS (HC * IN_CH / 8)        // 8,192

__device__ __forceinline__ uint32_t f2h2(float x, float y) {
    __half2 h = __floats2half2_rn(x, y);
    return *reinterpret_cast<uint32_t*>(&h);
}

// ---------------- W fp16 conversion (tiny, stream 0) ----------------
__global__ void cvt_w_kernel(const float* __restrict__ W) {
    int i = blockIdx.x * blockDim.x + threadIdx.x;
    if (i < W_CVT_THREADS) {
        size_t off = (size_t)i * 8;
        float4 a = *(const float4*)(W + off);
        float4 b = *(const float4*)(W + off + 4);
        uint4 h;
        h.x = f2h2(a.x, a.y); h.y = f2h2(a.z, a.w);
        h.z = f2h2(b.x, b.y); h.w = f2h2(b.z, b.w);
        *(uint4*)(g_w16 + off) = h;
    }
}

// ---------------- edge-chain init: detect dtype + zero deg (stream 2) ----
__global__ void init_edge_kernel(const int* ei_words) {
    int i = blockIdx.x * blockDim.x + threadIdx.x;
    if (i == 0) {
        int all0 = 1;
        for (int k = 0; k < 64; k++) {
            if (ei_words[2 * k + 1] != 0) { all0 = 0; break; }
        }
        g_is64 = all0;
    }
    if (i < N_NODES) g_deg[i] = 0;
}

// ---------------- tensor-core / async primitives ----------------
__device__ __forceinline__ void mma_f16(float* c, const uint32_t* a, const uint32_t* b) {
    asm volatile(
        "mma.sync.aligned.m16n8k16.row.col.f32.f16.f16.f32 "
        "{%0,%1,%2,%3}, {%4,%5,%6,%7}, {%8,%9}, {%0,%1,%2,%3};\n"
        : "+f"(c[0]), "+f"(c[1]), "+f"(c[2]), "+f"(c[3])
        : "r"(a[0]), "r"(a[1]), "r"(a[2]), "r"(a[3]), "r"(b[0]), "r"(b[1]));
}

__device__ __forceinline__ void ldsm_x4(uint32_t* r, uint32_t addr) {
    asm volatile("ldmatrix.sync.aligned.m8n8.x4.shared.b16 {%0,%1,%2,%3}, [%4];"
        : "=r"(r[0]), "=r"(r[1]), "=r"(r[2]), "=r"(r[3]) : "r"(addr));
}

__device__ __forceinline__ void cp_async16(uint32_t smem_dst, const void* gsrc) {
    asm volatile("cp.async.cg.shared.global [%0], [%1], 16;"
        :: "r"(smem_dst), "l"(gsrc) : "memory");
}
__device__ __forceinline__ void cp_commit() {
    asm volatile("cp.async.commit_group;" ::: "memory");
}
__device__ __forceinline__ void cp_wait0() {
    asm volatile("cp.async.wait_group 0;" ::: "memory");
}

// ---------------- GEMM: Wh = x @ W^T  (BM=128, BN=256, BK=64) ------------
// 512 threads, 16 warps (2x8). Warp tile 64x32 = one head wide.
// A: fp32 LDG -> inline cvt -> STS (double buffered).
// B: fp16 via cp.async (double buffered, overlaps MMA).
#define SA 36          // smem row stride in uint32 (LDSM conflict-free: 144B = 4 banks/row)
#define BUFA (128 * SA)
#define BUFB (256 * SA)

__global__ __launch_bounds__(512, 1)
void gemm_kernel(const float* __restrict__ x,
                 const float* __restrict__ aL, const float* __restrict__ aR) {
    __shared__ uint32_t As[2 * BUFA];
    __shared__ uint32_t Bs[2 * BUFB];

    const int t    = threadIdx.x;
    const int m0   = blockIdx.x * 128;
    const int wid  = t >> 5, lane = t & 31;
    const int wm   = wid >> 3, wn = wid & 7;    // 2 x 8 warp grid
    const int g    = lane >> 2, tt = lane & 3;

    // A loader: 128 rows x 64 k fp32; 16 fp32 per thread
    const int ra  = t >> 2;
    const int kqa = (t & 3) * 16;
    // B loader: 256 rows x 64 k fp16; 32 fp16 (64B) per thread via 4 cp.async
    const int rb  = t >> 1;
    const int kqb = (t & 1) * 32;

    float c[4][4][4];
    #pragma unroll
    for (int i = 0; i < 4; i++)
        #pragma unroll
        for (int j = 0; j < 4; j++)
            #pragma unroll
            for (int k = 0; k < 4; k++) c[i][j][k] = 0.0f;

    const int mid = lane >> 3;            // ldmatrix matrix id 0..3
    const uint32_t As_u = (uint32_t)__cvta_generic_to_shared(As);
    const uint32_t Bs_u = (uint32_t)__cvta_generic_to_shared(Bs);
    int a_off[4];
    #pragma unroll
    for (int fm = 0; fm < 4; fm++)
        a_off[fm] = (wm * 64 + fm * 16 + (mid & 1) * 8 + (lane & 7)) * SA + (mid >> 1) * 4;
    int b_off[2];
    #pragma unroll
    for (int p = 0; p < 2; p++)
        b_off[p] = (wn * 32 + p * 16 + (mid >> 1) * 8 + (lane & 7)) * SA + (mid & 1) * 4;

    const int am = min(m0 + ra, N_NODES - 1);   // clamp (dup rows, masked at store)
    uint4 va0, va1;
    auto loadA = [&](int k0) {
        const float4* pa = (const float4*)(x + (size_t)am * IN_CH + k0 + kqa);
        float4 a0 = pa[0], a1 = pa[1], a2 = pa[2], a3 = pa[3];
        va0.x = f2h2(a0.x, a0.y); va0.y = f2h2(a0.z, a0.w);
        va0.z = f2h2(a1.x, a1.y); va0.w = f2h2(a1.z, a1.w);
        va1.x = f2h2(a2.x, a2.y); va1.y = f2h2(a2.z, a2.w);
        va1.z = f2h2(a3.x, a3.y); va1.w = f2h2(a3.z, a3.w);
    };
    const int sa_sts = ra * SA + (kqa >> 1);
    auto stsA = [&](int buf) {
        int s = buf * BUFA + sa_sts;
        *(uint4*)&As[s]     = va0;
        *(uint4*)&As[s + 4] = va1;
    };
    const uint32_t b_dst = Bs_u + 4u * (uint32_t)(rb * SA + (kqb >> 1));
    auto cpB = [&](int k0, int buf) {
        const ushort* src = &g_w16[rb * IN_CH + k0 + kqb];
        uint32_t dst = b_dst + 4u * (uint32_t)(buf * BUFB);
        cp_async16(dst,      src);
        cp_async16(dst + 16, src + 8);
        cp_async16(dst + 32, src + 16);
        cp_async16(dst + 48, src + 24);
    };

    // prologue: stage 0
    cpB(0, 0);
    cp_commit();
    loadA(0);
    stsA(0);
    cp_wait0();
    __syncthreads();

    #pragma unroll
    for (int it = 0; it < IN_CH / 64; it++) {
        const int buf = it & 1;
        const bool more = (it + 1) < IN_CH / 64;
        if (more) {
            cpB((it + 1) * 64, buf ^ 1);   // async copy overlaps this iter's MMAs
            cp_commit();
            loadA((it + 1) * 64);          // LDG + cvt overlaps too
        }

        const uint32_t a_base = As_u + 4u * (uint32_t)(buf * BUFA);
        const uint32_t b_base = Bs_u + 4u * (uint32_t)(buf * BUFB);
        #pragma unroll
        for (int ks = 0; ks < 4; ks++) {
            const int kw = ks * 8;
            uint32_t bf[4][2];
            {
                uint32_t rr[4];
                ldsm_x4(rr, b_base + 4u * (b_off[0] + kw));
                bf[0][0] = rr[0]; bf[0][1] = rr[1]; bf[1][0] = rr[2]; bf[1][1] = rr[3];
                ldsm_x4(rr, b_base + 4u * (b_off[1] + kw));
                bf[2][0] = rr[0]; bf[2][1] = rr[1]; bf[3][0] = rr[2]; bf[3][1] = rr[3];
            }
            #pragma unroll
            for (int fm = 0; fm < 4; fm++) {
                uint32_t af[4];
                ldsm_x4(af, a_base + 4u * (a_off[fm] + kw));
                #pragma unroll
                for (int fn = 0; fn < 4; fn++)
                    mma_f16(c[fm][fn], af, bf[fn]);
            }
        }
        if (more) {
            stsA(buf ^ 1);
            cp_wait0();
        }
        __syncthreads();
    }

    // ---- epilogue: store fp16 Wh + fused eL/eR ----
    const int h = wn;   // global head for this warp
    float aLv[8], aRv[8];
    #pragma unroll
    for (int fn = 0; fn < 4; fn++) {
        int c0 = fn * 8 + 2 * tt;
        aLv[2 * fn]     = aL[h * 32 + c0];
        aLv[2 * fn + 1] = aL[h * 32 + c0 + 1];
        aRv[2 * fn]     = aR[h * 32 + c0];
        aRv[2 * fn + 1] = aR[h * 32 + c0 + 1];
    }

    #pragma unroll
    for (int fm = 0; fm < 4; fm++) {
        int mrow = m0 + wm * 64 + fm * 16 + g;
        #pragma unroll
        for (int fn = 0; fn < 4; fn++) {
            int colp = (wn * 32 + fn * 8 + 2 * tt) >> 1;  // half2 index
            if (mrow < N_NODES)
                g_Whh[(size_t)mrow * (HC / 2) + colp] =
                    __floats2half2_rn(c[fm][fn][0], c[fm][fn][1]);
            if (mrow + 8 < N_NODES)
                g_Whh[(size_t)(mrow + 8) * (HC / 2) + colp] =
                    __floats2half2_rn(c[fm][fn][2], c[fm][fn][3]);
        }
        #pragma unroll
        for (int half = 0; half < 2; half++) {
            float pl = 0.f, pr = 0.f;
            #pragma unroll
            for (int fn = 0; fn < 4; fn++) {
                pl += c[fm][fn][2 * half] * aLv[2 * fn] + c[fm][fn][2 * half + 1] * aLv[2 * fn + 1];
                pr += c[fm][fn][2 * half] * aRv[2 * fn] + c[fm][fn][2 * half + 1] * aRv[2 * fn + 1];
            }
            pl += __shfl_xor_sync(0xffffffffu, pl, 1);
            pl += __shfl_xor_sync(0xffffffffu, pl, 2);
            pr += __shfl_xor_sync(0xffffffffu, pr, 1);
            pr += __shfl_xor_sync(0xffffffffu, pr, 2);
            int m = mrow + half * 8;
            if (tt == 0 && m < N_NODES) {
                g_eL[m * HEADS + h] = pl;
                g_eR[m * HEADS + h] = pr;
            }
        }
    }
}

// ---------------- degree count: 4 edges / thread ----------------
__global__ void deg_kernel(const void* __restrict__ ei) {
    int e4 = blockIdx.x * blockDim.x + threadIdx.x;
    if (e4 * 4 >= N_EDGES) return;
    int d[4];
    if (g_is64) {
        const longlong2* p = (const longlong2*)((const long long*)ei + N_EDGES) + e4 * 2;
        longlong2 v0 = p[0], v1 = p[1];
        d[0] = (int)v0.x; d[1] = (int)v0.y; d[2] = (int)v1.x; d[3] = (int)v1.y;
    } else {
        int4 v = ((const int4*)((const int*)ei + N_EDGES))[e4];
        d[0] = v.x; d[1] = v.y; d[2] = v.z; d[3] = v.w;
    }
    #pragma unroll
    for (int i = 0; i < 4; i++) atomicAdd(&g_deg[d[i]], 1);
}

// ---------------- scan phase 1: per-block sums ----------
__global__ __launch_bounds__(SCAN_CHUNK)
void scan1_kernel() {
    __shared__ int wsum[SCAN_CHUNK / 32];
    int t = threadIdx.x, lane = t & 31, w = t >> 5;
    int idx = blockIdx.x * SCAN_CHUNK + t;
    int v = (idx < N_NODES) ? g_deg[idx] : 0;
    #pragma unroll
    for (int off = 16; off > 0; off >>= 1) v += __shfl_down_sync(0xffffffffu, v, off);
    if (lane == 0) wsum[w] = v;
    __syncthreads();
    if (t < SCAN_CHUNK / 32) {
        int s = wsum[t];
        #pragma unroll
        for (int off = 8; off > 0; off >>= 1) s += __shfl_down_sync(0xffffu, s, off);
        if (t == 0) g_blocksum[blockIdx.x] = s;
    }
}

// ---------------- scan phase 3: block-local scan + inline block offset ----
__global__ __launch_bounds__(SCAN_CHUNK)
void scan3_kernel() {
    __shared__ int wsum[SCAN_CHUNK / 32];
    __shared__ int s_boff;
    int t = threadIdx.x, lane = t & 31, w = t >> 5;

    if (w == 0) {
        int s = 0;
        for (int j = lane; j < blockIdx.x; j += 32) s += g_blocksum[j];
        #pragma unroll
        for (int off = 16; off > 0; off >>= 1) s += __shfl_down_sync(0xffffffffu, s, off);
        if (lane == 0) s_boff = s;
    }

    int idx = blockIdx.x * SCAN_CHUNK + t;
    int v = (idx < N_NODES) ? g_deg[idx] : 0;
    int incl = v;
    #pragma unroll
    for (int off = 1; off < 32; off <<= 1) {
        int nb = __shfl_up_sync(0xffffffffu, incl, off);
        if (lane >= off) incl += nb;
    }
    if (lane == 31) wsum[w] = incl;
    __syncthreads();
    if (t < SCAN_CHUNK / 32) {
        int s = wsum[t];
        #pragma unroll
        for (int off = 1; off < SCAN_CHUNK / 32; off <<= 1) {
            int nb = __shfl_up_sync(0xffffu, s, off);
            if ((t & 15) >= off) s += nb;
        }
        wsum[t] = s;
    }
    __syncthreads();
    int incl_tot = incl + (w ? wsum[w - 1] : 0) + s_boff;
    if (idx < N_NODES) {
        g_cursor[idx]   = incl_tot - v;
        g_ptr[idx + 1]  = incl_tot;
    }
    if (idx == 0) g_ptr[0] = 0;
}

// ---------------- CSR fill: 4 edges / thread ----------------
__global__ void scatter_kernel(const void* __restrict__ ei) {
    int e4 = blockIdx.x * blockDim.x + threadIdx.x;
    if (e4 * 4 >= N_EDGES) return;
    int s[4], d[4];
    if (g_is64) {
        const longlong2* ps = (const longlong2*)ei + e4 * 2;
        const longlong2* pd = (const longlong2*)((const long long*)ei + N_EDGES) + e4 * 2;
        longlong2 s0 = ps[0], s1 = ps[1], d0 = pd[0], d1 = pd[1];
        s[0] = (int)s0.x; s[1] = (int)s0.y; s[2] = (int)s1.x; s[3] = (int)s1.y;
        d[0] = (int)d0.x; d[1] = (int)d0.y; d[2] = (int)d1.x; d[3] = (int)d1.y;
    } else {
        int4 vs = ((const int4*)ei)[e4];
        int4 vd = ((const int4*)((const int*)ei + N_EDGES))[e4];
        s[0] = vs.x; s[1] = vs.y; s[2] = vs.z; s[3] = vs.w;
        d[0] = vd.x; d[1] = vd.y; d[2] = vd.z; d[3] = vd.w;
    }
    #pragma unroll
    for (int i = 0; i < 4; i++) {
        int pos = atomicAdd(&g_cursor[d[i]], 1);
        g_csr_src[pos] = s[i];
    }
}

// ---------------- aggregation: warp-per-node, 8-wide batched FMA loop ----
__device__ __forceinline__ void fma_row(float* acc, float w, uint4 v) {
    float2 f0 = __half22float2(*reinterpret_cast<const __half2*>(&v.x));
    float2 f1 = __half22float2(*reinterpret_cast<const __half2*>(&v.y));
    float2 f2 = __half22float2(*reinterpret_cast<const __half2*>(&v.z));
    float2 f3 = __half22float2(*reinterpret_cast<const __half2*>(&v.w));
    acc[0] = fmaf(w, f0.x, acc[0]); acc[1] = fmaf(w, f0.y, acc[1]);
    acc[2] = fmaf(w, f1.x, acc[2]); acc[3] = fmaf(w, f1.y, acc[3]);
    acc[4] = fmaf(w, f2.x, acc[4]); acc[5] = fmaf(w, f2.y, acc[5]);
    acc[6] = fmaf(w, f3.x, acc[6]); acc[7] = fmaf(w, f3.y, acc[7]);
}

__global__ __launch_bounds__(256)
void agg_kernel(float* __restrict__ out) {
    __shared__ float s_w[8][32][9];   // [warp][edge][head], stride 9: conflict-free

    const int lane = threadIdx.x & 31;
    const int wix  = threadIdx.x >> 5;            // warp in block
    const int n = blockIdx.x * 8 + wix;
    if (n >= N_NODES) return;

    const int hq = lane >> 2;                     // head for FMA phase (channels)

    float er[8];
    {
        float4 r0 = *(const float4*)&g_eR[n * HEADS];
        float4 r1 = *(const float4*)&g_eR[n * HEADS + 4];
        er[0] = r0.x; er[1] = r0.y; er[2] = r0.z; er[3] = r0.w;
        er[4] = r1.x; er[5] = r1.y; er[6] = r1.z; er[7] = r1.w;
    }

    float acc[8];
    float denom;
    {
        float4 l0 = *(const float4*)&g_eL[n * HEADS];
        float4 l1 = *(const float4*)&g_eL[n * HEADS + 4];
        float el[8] = {l0.x, l0.y, l0.z, l0.w, l1.x, l1.y, l1.z, l1.w};
        float s = el[hq] + er[hq];
        s = fmaxf(s, NEG_SLOPE * s);
        float wself = __expf(s);
        uint4 v = ((const uint4*)&g_Whh[(size_t)n * (HC / 2)])[lane];
        float2 f0 = __half22float2(*reinterpret_cast<const __half2*>(&v.x));
        float2 f1 = __half22float2(*reinterpret_cast<const __half2*>(&v.y));
        float2 f2 = __half22float2(*reinterpret_cast<const __half2*>(&v.z));
        float2 f3 = __half22float2(*reinterpret_cast<const __half2*>(&v.w));
        acc[0] = wself * f0.x; acc[1] = wself * f0.y;
        acc[2] = wself * f1.x; acc[3] = wself * f1.y;
        acc[4] = wself * f2.x; acc[5] = wself * f2.y;
        acc[6] = wself * f3.x; acc[7] = wself * f3.y;
        denom = wself;
    }

    const int beg = g_ptr[n];
    const int end = g_ptr[n + 1];

    for (int base = beg; base < end; base += 32) {
        int cnt = min(32, end - base);
        int src_l = 0;
        if (lane < cnt) {
            src_l = g_csr_src[base + lane];
            float4 l0 = *(const float4*)&g_eL[src_l * HEADS];
            float4 l1 = *(const float4*)&g_eL[src_l * HEADS + 4];
            float el[8] = {l0.x, l0.y, l0.z, l0.w, l1.x, l1.y, l1.z, l1.w};
            #pragma unroll
            for (int h = 0; h < 8; h++) {
                float s = el[h] + er[h];
                s = fmaxf(s, NEG_SLOPE * s);
                s_w[wix][lane][h] = __expf(s);
            }
        }
        __syncwarp();

        int k = 0;
        for (; k + 8 <= cnt; k += 8) {
            int s0 = __shfl_sync(0xffffffffu, src_l, k);
            int s1 = __shfl_sync(0xffffffffu, src_l, k + 1);
            int s2 = __shfl_sync(0xffffffffu, src_l, k + 2);
            int s3 = __shfl_sync(0xffffffffu, src_l, k + 3);
            int s4 = __shfl_sync(0xffffffffu, src_l, k + 4);
            int s5 = __shfl_sync(0xffffffffu, src_l, k + 5);
            int s6 = __shfl_sync(0xffffffffu, src_l, k + 6);
            int s7 = __shfl_sync(0xffffffffu, src_l, k + 7);
            uint4 v0 = ((const uint4*)&g_Whh[(size_t)s0 * (HC / 2)])[lane];
            uint4 v1 = ((const uint4*)&g_Whh[(size_t)s1 * (HC / 2)])[lane];
            uint4 v2 = ((const uint4*)&g_Whh[(size_t)s2 * (HC / 2)])[lane];
            uint4 v3 = ((const uint4*)&g_Whh[(size_t)s3 * (HC / 2)])[lane];
            uint4 v4 = ((const uint4*)&g_Whh[(size_t)s4 * (HC / 2)])[lane];
            uint4 v5 = ((const uint4*)&g_Whh[(size_t)s5 * (HC / 2)])[lane];
            uint4 v6 = ((const uint4*)&g_Whh[(size_t)s6 * (HC / 2)])[lane];
            uint4 v7 = ((const uint4*)&g_Whh[(size_t)s7 * (HC / 2)])[lane];
            float w0 = s_w[wix][k][hq],     w1 = s_w[wix][k + 1][hq];
            float w2 = s_w[wix][k + 2][hq], w3 = s_w[wix][k + 3][hq];
            float w4 = s_w[wix][k + 4][hq], w5 = s_w[wix][k + 5][hq];
            float w6 = s_w[wix][k + 6][hq], w7 = s_w[wix][k + 7][hq];
            fma_row(acc, w0, v0); denom += w0;
            fma_row(acc, w1, v1); denom += w1;
            fma_row(acc, w2, v2); denom += w2;
            fma_row(acc, w3, v3); denom += w3;
            fma_row(acc, w4, v4); denom += w4;
            fma_row(acc, w5, v5); denom += w5;
            fma_row(acc, w6, v6); denom += w6;
            fma_row(acc, w7, v7); denom += w7;
        }
        for (; k + 4 <= cnt; k += 4) {
            int s0 = __shfl_sync(0xffffffffu, src_l, k);
            int s1 = __shfl_sync(0xffffffffu, src_l, k + 1);
            int s2 = __shfl_sync(0xffffffffu, src_l, k + 2);
            int s3 = __shfl_sync(0xffffffffu, src_l, k + 3);
            uint4 v0 = ((const uint4*)&g_Whh[(size_t)s0 * (HC / 2)])[lane];
            uint4 v1 = ((const uint4*)&g_Whh[(size_t)s1 * (HC / 2)])[lane];
            uint4 v2 = ((const uint4*)&g_Whh[(size_t)s2 * (HC / 2)])[lane];
            uint4 v3 = ((const uint4*)&g_Whh[(size_t)s3 * (HC / 2)])[lane];
            float w0 = s_w[wix][k][hq],     w1 = s_w[wix][k + 1][hq];
            float w2 = s_w[wix][k + 2][hq], w3 = s_w[wix][k + 3][hq];
            fma_row(acc, w0, v0); denom += w0;
            fma_row(acc, w1, v1); denom += w1;
            fma_row(acc, w2, v2); denom += w2;
            fma_row(acc, w3, v3); denom += w3;
        }
        for (; k < cnt; k++) {
            int src = __shfl_sync(0xffffffffu, src_l, k);
            float w = s_w[wix][k][hq];
            uint4 v = ((const uint4*)&g_Whh[(size_t)src * (HC / 2)])[lane];
            fma_row(acc, w, v);
            denom += w;
        }
        __syncwarp();
    }

    float inv = 1.0f / (denom + 1e-16f);
    float* op = out + (size_t)n * HC + lane * 8;
    *(float4*)op       = make_float4(acc[0] * inv, acc[1] * inv, acc[2] * inv, acc[3] * inv);
    *(float4*)(op + 4) = make_float4(acc[4] * inv, acc[5] * inv, acc[6] * inv, acc[7] * inv);
}

// ---------------- launch: forked-capture dual stream ----------------
extern "C" void kernel_launch(void* const* d_in, const int* in_sizes, int n_in,
                              void* d_out, int out_size) {
    const float* x  = (const float*)d_in[0];
    const void*  ei = (const void*)d_in[1];
    const float* W  = (const float*)d_in[2];
    const float* aL = (const float*)d_in[3];
    const float* aR = (const float*)d_in[4];
    float* out = (float*)d_out;

    cudaStream_t s2;
    cudaStreamCreateWithFlags(&s2, cudaStreamNonBlocking);
    cudaEvent_t eFork, eJoin;
    cudaEventCreateWithFlags(&eFork, cudaEventDisableTiming);
    cudaEventCreateWithFlags(&eJoin, cudaEventDisableTiming);

    // fork: edge-prep chain on s2, gemm chain on default stream
    cudaEventRecord(eFork, 0);
    cudaStreamWaitEvent(s2, eFork, 0);

    cvt_w_kernel<<<(W_CVT_THREADS + 255) / 256, 256>>>(W);                          // 0 (s0)
    init_edge_kernel<<<(N_NODES + 255) / 256, 256, 0, s2>>>((const int*)ei);        // 1 (s2)
    deg_kernel<<<(N_EDGES / 4 + 255) / 256, 256, 0, s2>>>(ei);                      // 2 (s2)

    gemm_kernel<<<(N_NODES + 127) / 128, 512>>>(x, aL, aR);                         // 3 (s0) <- profiled

    scan1_kernel<<<SCAN_BLOCKS, SCAN_CHUNK, 0, s2>>>();                             // 4 (s2)
    scan3_kernel<<<SCAN_BLOCKS, SCAN_CHUNK, 0, s2>>>();                             // 5 (s2)
    scatter_kernel<<<(N_EDGES / 4 + 255) / 256, 256, 0, s2>>>(ei);                  // 6 (s2)
    cudaEventRecord(eJoin, s2);

    // join: agg needs CSR (s2) + Wh/eL/eR (s0)
    cudaStreamWaitEvent(0, eJoin, 0);
    agg_kernel<<<(N_NODES + 7) / 8, 256>>>(out);                                    // 7 (s0)

    cudaEventDestroy(eFork);
    cudaEventDestroy(eJoin);
    cudaStreamDestroy(s2);
}